// round 3
// baseline (speedup 1.0000x reference)
#include <cuda_runtime.h>
#include <cstdint>
#include <math.h>

#define D 128
#define G 100
#define NLAYERS 6
#define ZDIM 133
#define IND 5
#define NMAX 20000
#define EMAX 320000
#define LOG2F_ 0.6931471805599453f

// ---------------- scratch (no allocations allowed) ----------------
__device__ __align__(256) float g_h [NMAX * D];
__device__ __align__(256) float g_xf[NMAX * D];
__device__ __align__(256) float g_mi[NMAX * D];

__device__ __forceinline__ float ssp_f(float x) {
    // softplus(x) - log(2), stable
    float sp = (x > 15.0f) ? x : log1pf(__expf(x));
    return sp - LOG2F_;
}

// ---------------- embed: h = z[:, :5] @ Wemb^T + b + z[:, 5:] ----------------
__global__ void embed_kernel(const float* __restrict__ z,
                             const float* __restrict__ w,
                             const float* __restrict__ b, int N) {
    int gid = blockIdx.x * blockDim.x + threadIdx.x;
    if (gid >= N * D) return;
    int i = gid >> 7, d = gid & 127;
    const float* zr = z + (size_t)i * ZDIM;
    float acc = b[d] + zr[IND + d];
#pragma unroll
    for (int k = 0; k < IND; k++) acc += zr[k] * w[d * IND + k];
    g_h[gid] = acc;
}

// ---------------- xf = h @ lin1^T ; also zeros m_i rows ----------------
// smem: lin1 transposed [k][d] (64KB) + h tile [64][128] (32KB)
__global__ void xf_kernel(const float* __restrict__ lin1, int N) {
    extern __shared__ float smem[];
    float* wt = smem;            // [D][D] transposed: wt[k*D+d] = lin1[d][k]
    float* hs = wt + D * D;      // [64][D]
    int tid = threadIdx.x;

    for (int idx = tid; idx < D * D; idx += 256) {
        int d = idx >> 7, k = idx & 127;
        wt[k * D + d] = lin1[idx];
    }

    int tx = tid & 31, ty = tid >> 5;
    int ntiles = (N + 63) >> 6;
    for (int t = blockIdx.x; t < ntiles; t += gridDim.x) {
        int r0 = t << 6;
        __syncthreads();
        for (int idx = tid; idx < 64 * D; idx += 256) {
            int r = r0 + (idx >> 7);
            hs[idx] = (r < N) ? g_h[r * D + (idx & 127)] : 0.f;
        }
        // zero m_i rows for this tile
        for (int idx = tid; idx < 64 * 32; idx += 256) {
            int r = r0 + (idx >> 5);
            if (r < N)
                reinterpret_cast<float4*>(g_mi)[r * 32 + (idx & 31)] =
                    make_float4(0.f, 0.f, 0.f, 0.f);
        }
        __syncthreads();

        float4 acc[8];
#pragma unroll
        for (int j = 0; j < 8; j++) acc[j] = make_float4(0.f, 0.f, 0.f, 0.f);
#pragma unroll 4
        for (int k = 0; k < D; k++) {
            float4 w = *reinterpret_cast<const float4*>(&wt[k * D + tx * 4]);
#pragma unroll
            for (int j = 0; j < 8; j++) {
                float a = hs[(ty * 8 + j) * D + k];
                acc[j].x += a * w.x; acc[j].y += a * w.y;
                acc[j].z += a * w.z; acc[j].w += a * w.w;
            }
        }
#pragma unroll
        for (int j = 0; j < 8; j++) {
            int r = r0 + ty * 8 + j;
            if (r < N)
                *reinterpret_cast<float4*>(&g_xf[r * D + tx * 4]) = acc[j];
        }
    }
}

// ---------------- fused edge kernel ----------------
// hidden = ssp(attr @ W1^T + b1); Wf = (hidden @ W2^T + b2) * C;
// m_ij = xf[src] * Wf; red-add into m_i[dst]
__global__ void edge_kernel(const float* __restrict__ attr,
                            const int* __restrict__ eidx,
                            const float* __restrict__ elen,
                            const float* __restrict__ w1,
                            const float* __restrict__ b1,
                            const float* __restrict__ w2,
                            const float* __restrict__ b2, int E) {
    extern __shared__ float smem[];
    float* w1t   = smem;                 // [G][D]
    float* w2t   = w1t + G * D;          // [D][D]
    float* b1s   = w2t + D * D;          // [D]
    float* b2s   = b1s + D;              // [D]
    float* attrs = b2s + D;              // [64][G]
    float* hids  = attrs + 64 * G;       // [64][D]
    int*   srcs  = (int*)(hids + 64 * D);
    int*   dsts  = srcs + 64;
    float* cs    = (float*)(dsts + 64);

    int tid = threadIdx.x;
    for (int idx = tid; idx < D * G; idx += 256) {
        int d = idx / G, g = idx - d * G;
        w1t[g * D + d] = w1[idx];
    }
    for (int idx = tid; idx < D * D; idx += 256) {
        int d = idx >> 7, k = idx & 127;
        w2t[k * D + d] = w2[idx];
    }
    if (tid < D) { b1s[tid] = b1[tid]; b2s[tid] = b2[tid]; }

    int tx = tid & 31, ty = tid >> 5;
    int ntiles = (E + 63) >> 6;
    for (int t = blockIdx.x; t < ntiles; t += gridDim.x) {
        int e0 = t << 6;
        __syncthreads();
        for (int idx = tid; idx < 64 * G; idx += 256) {
            int e = e0 + idx / G;
            attrs[idx] = (e < E) ? attr[(size_t)e0 * G + idx] : 0.f;
        }
        if (tid < 64) {
            int e = e0 + tid;
            if (e < E) {
                srcs[tid] = eidx[e];
                dsts[tid] = eidx[E + e];
                cs[tid]   = (elen[e] <= 10.0f) ? 1.0f : 0.0f;
            } else { srcs[tid] = 0; dsts[tid] = 0; cs[tid] = 0.f; }
        }
        __syncthreads();

        // GEMM1: hidden[64][128] over G
        float4 acc[8];
#pragma unroll
        for (int j = 0; j < 8; j++) acc[j] = make_float4(0.f, 0.f, 0.f, 0.f);
#pragma unroll 4
        for (int g = 0; g < G; g++) {
            float4 w = *reinterpret_cast<const float4*>(&w1t[g * D + tx * 4]);
#pragma unroll
            for (int j = 0; j < 8; j++) {
                float a = attrs[(ty * 8 + j) * G + g];
                acc[j].x += a * w.x; acc[j].y += a * w.y;
                acc[j].z += a * w.z; acc[j].w += a * w.w;
            }
        }
        float4 bb1 = *reinterpret_cast<const float4*>(&b1s[tx * 4]);
#pragma unroll
        for (int j = 0; j < 8; j++) {
            float4 v;
            v.x = ssp_f(acc[j].x + bb1.x);
            v.y = ssp_f(acc[j].y + bb1.y);
            v.z = ssp_f(acc[j].z + bb1.z);
            v.w = ssp_f(acc[j].w + bb1.w);
            *reinterpret_cast<float4*>(&hids[(ty * 8 + j) * D + tx * 4]) = v;
        }
        __syncthreads();

        // GEMM2: Wf over D, then gather-multiply-scatter
#pragma unroll
        for (int j = 0; j < 8; j++) acc[j] = make_float4(0.f, 0.f, 0.f, 0.f);
#pragma unroll 4
        for (int k = 0; k < D; k++) {
            float4 w = *reinterpret_cast<const float4*>(&w2t[k * D + tx * 4]);
#pragma unroll
            for (int j = 0; j < 8; j++) {
                float a = hids[(ty * 8 + j) * D + k];
                acc[j].x += a * w.x; acc[j].y += a * w.y;
                acc[j].z += a * w.z; acc[j].w += a * w.w;
            }
        }
        float4 bb2 = *reinterpret_cast<const float4*>(&b2s[tx * 4]);
#pragma unroll
        for (int j = 0; j < 8; j++) {
            int el = ty * 8 + j;
            int e  = e0 + el;
            if (e < E) {
                float c = cs[el];
                float wfx = (acc[j].x + bb2.x) * c;
                float wfy = (acc[j].y + bb2.y) * c;
                float wfz = (acc[j].z + bb2.z) * c;
                float wfw = (acc[j].w + bb2.w) * c;
                const float4 xv = *reinterpret_cast<const float4*>(
                    &g_xf[(size_t)srcs[el] * D + tx * 4]);
                float rx = wfx * xv.x, ry = wfy * xv.y;
                float rz = wfz * xv.z, rw = wfw * xv.w;
                float* p = &g_mi[(size_t)dsts[el] * D + tx * 4];
                asm volatile("red.global.add.v4.f32 [%0], {%1,%2,%3,%4};"
                             :: "l"(p), "f"(rx), "f"(ry), "f"(rz), "f"(rw)
                             : "memory");
            }
        }
    }
}

// ---------------- fused update ----------------
// m = ssp(m_i @ lin2^T + lin2_b); h_out = h + h@lwA^T + m@lwB^T + lin_b
__global__ void update_kernel(const float* __restrict__ lin2w,
                              const float* __restrict__ lin2b,
                              const float* __restrict__ linw,
                              const float* __restrict__ linb,
                              int N, float* __restrict__ hout) {
    extern __shared__ float smem[];
    float* l2t = smem;             // [k][d]
    float* lat = l2t + D * D;      // [k][d] (cols 0:128 of lin_w -> multiplies h)
    float* lbt = lat + D * D;      // [k][d] (cols 128:256 -> multiplies m)
    float* b2s = lbt + D * D;      // [D]
    float* bls = b2s + D;          // [D]
    float* hsm = bls + D;          // [32][D]
    float* msm = hsm + 32 * D;     // [32][D], mi then m (in place)
    int tid = threadIdx.x;

    for (int idx = tid; idx < D * D; idx += 256) {
        int d = idx >> 7, k = idx & 127;
        l2t[k * D + d] = lin2w[idx];
    }
    for (int idx = tid; idx < D * 2 * D; idx += 256) {
        int d = idx >> 8, c = idx & 255;
        float v = linw[idx];
        if (c < D) lat[c * D + d] = v;
        else       lbt[(c - D) * D + d] = v;
    }
    if (tid < D) { b2s[tid] = lin2b[tid]; bls[tid] = linb[tid]; }

    int tx = tid & 31, ty = tid >> 5;
    int ntiles = (N + 31) >> 5;
    for (int t = blockIdx.x; t < ntiles; t += gridDim.x) {
        int r0 = t << 5;
        __syncthreads();
        for (int idx = tid; idx < 32 * D; idx += 256) {
            int r = r0 + (idx >> 7);
            hsm[idx] = (r < N) ? g_h[r * D + (idx & 127)] : 0.f;
            msm[idx] = (r < N) ? g_mi[r * D + (idx & 127)] : 0.f;
        }
        __syncthreads();

        // phase 1: m tile (4 rows x 4 cols per thread)
        float4 a[4];
#pragma unroll
        for (int j = 0; j < 4; j++) a[j] = make_float4(0.f, 0.f, 0.f, 0.f);
#pragma unroll 4
        for (int k = 0; k < D; k++) {
            float4 w = *reinterpret_cast<const float4*>(&l2t[k * D + tx * 4]);
#pragma unroll
            for (int j = 0; j < 4; j++) {
                float v = msm[(ty * 4 + j) * D + k];
                a[j].x += v * w.x; a[j].y += v * w.y;
                a[j].z += v * w.z; a[j].w += v * w.w;
            }
        }
        float4 b2v = *reinterpret_cast<const float4*>(&b2s[tx * 4]);
        float4 mval[4];
#pragma unroll
        for (int j = 0; j < 4; j++) {
            mval[j].x = ssp_f(a[j].x + b2v.x);
            mval[j].y = ssp_f(a[j].y + b2v.y);
            mval[j].z = ssp_f(a[j].z + b2v.z);
            mval[j].w = ssp_f(a[j].w + b2v.w);
        }
        __syncthreads();   // all reads of mi done
#pragma unroll
        for (int j = 0; j < 4; j++)
            *reinterpret_cast<float4*>(&msm[(ty * 4 + j) * D + tx * 4]) = mval[j];
        __syncthreads();

        // phase 2: out = h + h@lwA^T + m@lwB^T + lin_b
        float4 o[4];
        float4 blv = *reinterpret_cast<const float4*>(&bls[tx * 4]);
#pragma unroll
        for (int j = 0; j < 4; j++) {
            float4 h0 = *reinterpret_cast<const float4*>(
                &hsm[(ty * 4 + j) * D + tx * 4]);
            o[j].x = h0.x + blv.x; o[j].y = h0.y + blv.y;
            o[j].z = h0.z + blv.z; o[j].w = h0.w + blv.w;
        }
#pragma unroll 4
        for (int k = 0; k < D; k++) {
            float4 wa = *reinterpret_cast<const float4*>(&lat[k * D + tx * 4]);
            float4 wb = *reinterpret_cast<const float4*>(&lbt[k * D + tx * 4]);
#pragma unroll
            for (int j = 0; j < 4; j++) {
                float hv = hsm[(ty * 4 + j) * D + k];
                float mv = msm[(ty * 4 + j) * D + k];
                o[j].x += hv * wa.x + mv * wb.x;
                o[j].y += hv * wa.y + mv * wb.y;
                o[j].z += hv * wa.z + mv * wb.z;
                o[j].w += hv * wa.w + mv * wb.w;
            }
        }
        float* outp = hout ? hout : g_h;
#pragma unroll
        for (int j = 0; j < 4; j++) {
            int r = r0 + ty * 4 + j;
            if (r < N)
                *reinterpret_cast<float4*>(&outp[r * D + tx * 4]) = o[j];
        }
    }
}

// ---------------- launch ----------------
extern "C" void kernel_launch(void* const* d_in, const int* in_sizes, int n_in,
                              void* d_out, int out_size) {
    const float* z    = (const float*)d_in[0];
    const int*   eidx = (const int*)d_in[1];     // int32! (JAX x64 disabled)
    const float* elen = (const float*)d_in[2];
    const float* attr = (const float*)d_in[3];
    const float* embw = (const float*)d_in[4];
    const float* embb = (const float*)d_in[5];
    const float* w1   = (const float*)d_in[6];
    const float* b1   = (const float*)d_in[7];
    const float* w2   = (const float*)d_in[8];
    const float* b2   = (const float*)d_in[9];
    const float* l1w  = (const float*)d_in[10];
    const float* l2w  = (const float*)d_in[11];
    const float* l2b  = (const float*)d_in[12];
    const float* lw   = (const float*)d_in[13];
    const float* lb   = (const float*)d_in[14];

    int N = in_sizes[0] / ZDIM;
    int E = in_sizes[2];

    const int XF_SMEM   = (D * D + 64 * D) * 4;                       // 98304
    const int EDGE_SMEM = (G * D + D * D + 2 * D + 64 * G + 64 * D) * 4
                          + 64 * 4 * 3;                               // 176896
    const int UPD_SMEM  = (3 * D * D + 2 * D + 64 * D) * 4;           // 230400

    cudaFuncSetAttribute(xf_kernel,     cudaFuncAttributeMaxDynamicSharedMemorySize, XF_SMEM);
    cudaFuncSetAttribute(edge_kernel,   cudaFuncAttributeMaxDynamicSharedMemorySize, EDGE_SMEM);
    cudaFuncSetAttribute(update_kernel, cudaFuncAttributeMaxDynamicSharedMemorySize, UPD_SMEM);

    int nsm = 148;
    cudaDeviceGetAttribute(&nsm, cudaDevAttrMultiProcessorCount, 0);

    int etiles = (E + 63) >> 6;
    int xtiles = (N + 63) >> 6;
    int utiles = (N + 31) >> 5;
    int gx = 2 * nsm < xtiles ? 2 * nsm : xtiles;
    int ge = nsm < etiles ? nsm : etiles;
    int gu = nsm < utiles ? nsm : utiles;

    embed_kernel<<<(N * D + 255) / 256, 256>>>(z, embw, embb, N);

    for (int l = 0; l < NLAYERS; l++) {
        xf_kernel<<<gx, 256, XF_SMEM>>>(l1w + (size_t)l * D * D, N);
        edge_kernel<<<ge, 256, EDGE_SMEM>>>(attr, eidx, elen,
                                            w1 + (size_t)l * D * G, b1 + (size_t)l * D,
                                            w2 + (size_t)l * D * D, b2 + (size_t)l * D, E);
        float* hout = (l == NLAYERS - 1) ? (float*)d_out : nullptr;
        update_kernel<<<gu, 256, UPD_SMEM>>>(l2w + (size_t)l * D * D, l2b + (size_t)l * D,
                                             lw + (size_t)l * D * 2 * D, lb + (size_t)l * D,
                                             N, hout);
    }
}

// round 6
// speedup vs baseline: 1.5764x; 1.5764x over previous
#include <cuda_runtime.h>
#include <cstdint>
#include <math.h>

#define D 128
#define G 100
#define NLAYERS 6
#define ZDIM 133
#define IND 5
#define NMAX 20000
#define EMAX 320000
#define LOG2F_ 0.6931471805599453f

extern __shared__ char dynsmem[];

// ---------------- scratch ----------------
__device__ __align__(256) float g_h [NMAX * D];
__device__ __align__(256) float g_xf[NMAX * D];
__device__ __align__(256) float g_mi[NMAX * D];

__device__ __forceinline__ float ssp_f(float x) {
    float sp = (x > 15.0f) ? x : log1pf(__expf(x));
    return sp - LOG2F_;
}

__device__ __forceinline__ float tf32r(float x) {
    asm("cvt.rna.tf32.f32 %0, %1;" : "=f"(x) : "f"(x));
    return x;
}

// D = A(16x8) * B(8x8) + C,  tf32 operands, f32 accum
__device__ __forceinline__ void mma_tf32(float* d, const uint32_t* a,
                                         const uint32_t* b, const float* c) {
    asm volatile(
        "mma.sync.aligned.m16n8k8.row.col.f32.tf32.tf32.f32 "
        "{%0,%1,%2,%3}, {%4,%5,%6,%7}, {%8,%9}, {%10,%11,%12,%13};"
        : "=f"(d[0]), "=f"(d[1]), "=f"(d[2]), "=f"(d[3])
        : "r"(a[0]), "r"(a[1]), "r"(a[2]), "r"(a[3]),
          "r"(b[0]), "r"(b[1]),
          "f"(c[0]), "f"(c[1]), "f"(c[2]), "f"(c[3]));
}

// ---------------- embed ----------------
__global__ void embed_kernel(const float* __restrict__ z,
                             const float* __restrict__ w,
                             const float* __restrict__ b, int N) {
    int gid = blockIdx.x * blockDim.x + threadIdx.x;
    if (gid >= N * D) return;
    int i = gid >> 7, d = gid & 127;
    const float* zr = z + (size_t)i * ZDIM;
    float acc = b[d] + zr[IND + d];
#pragma unroll
    for (int k = 0; k < IND; k++) acc += zr[k] * w[d * IND + k];
    g_h[gid] = acc;
}

// ---------------- xf = h @ lin1^T ; zero m_i ----------------
__global__ void xf_kernel(const float* __restrict__ lin1, int N) {
    float* smem = reinterpret_cast<float*>(dynsmem);
    float* wt = smem;
    float* hs = wt + D * D;
    int tid = threadIdx.x;
    for (int idx = tid; idx < D * D; idx += 256) {
        int d = idx >> 7, k = idx & 127;
        wt[k * D + d] = lin1[idx];
    }
    int tx = tid & 31, ty = tid >> 5;
    int ntiles = (N + 63) >> 6;
    for (int t = blockIdx.x; t < ntiles; t += gridDim.x) {
        int r0 = t << 6;
        __syncthreads();
        for (int idx = tid; idx < 64 * D; idx += 256) {
            int r = r0 + (idx >> 7);
            hs[idx] = (r < N) ? g_h[r * D + (idx & 127)] : 0.f;
        }
        for (int idx = tid; idx < 64 * 32; idx += 256) {
            int r = r0 + (idx >> 5);
            if (r < N)
                reinterpret_cast<float4*>(g_mi)[r * 32 + (idx & 31)] =
                    make_float4(0.f, 0.f, 0.f, 0.f);
        }
        __syncthreads();
        float4 acc[8];
#pragma unroll
        for (int j = 0; j < 8; j++) acc[j] = make_float4(0.f, 0.f, 0.f, 0.f);
#pragma unroll 4
        for (int k = 0; k < D; k++) {
            float4 w = *reinterpret_cast<const float4*>(&wt[k * D + tx * 4]);
#pragma unroll
            for (int j = 0; j < 8; j++) {
                float a = hs[(ty * 8 + j) * D + k];
                acc[j].x += a * w.x; acc[j].y += a * w.y;
                acc[j].z += a * w.z; acc[j].w += a * w.w;
            }
        }
#pragma unroll
        for (int j = 0; j < 8; j++) {
            int r = r0 + ty * 8 + j;
            if (r < N)
                *reinterpret_cast<float4*>(&g_xf[r * D + tx * 4]) = acc[j];
        }
    }
}

// ---------------- tf32 mma.sync edge kernel ----------------
// smem (floats):
//   HA  [128][132]   attr / hidden / Wf (reused)      16896
//   W1t [104][136]   (k-major, padded K 100->104)     14144
//   W2t [128][136]                                    17408
//   b1s[128] b2s[128] srcs[128] dsts[128] cs[128]       640
//   total 49088 floats = 196352 bytes
#define SA 132
#define SW 136
#define OFF_W1 16896
#define OFF_W2 31040
#define OFF_B1 48448
#define OFF_B2 48576
#define OFF_SRC 48704
#define OFF_DST 48832
#define OFF_CS  48960
#define EDGE_SMEM (49088 * 4)

__global__ __launch_bounds__(256, 1)
void edge_kernel(const float* __restrict__ attr,
                 const int* __restrict__ eidx,
                 const float* __restrict__ elen,
                 const float* __restrict__ w1,
                 const float* __restrict__ b1,
                 const float* __restrict__ w2,
                 const float* __restrict__ b2, int E) {
    float* sm  = reinterpret_cast<float*>(dynsmem);
    float* HA  = sm;
    float* W1t = sm + OFF_W1;
    float* W2t = sm + OFF_W2;
    float* b1s = sm + OFF_B1;
    float* b2s = sm + OFF_B2;
    int*   srcs = reinterpret_cast<int*>(sm + OFF_SRC);
    int*   dsts = reinterpret_cast<int*>(sm + OFF_DST);
    float* cs   = sm + OFF_CS;

    int tid = threadIdx.x, lane = tid & 31, wid = tid >> 5;
    int wm = (wid & 3) * 32;       // row base of this warp's 32x64 tile
    int wn = (wid >> 2) * 64;      // col base
    int qr = lane >> 2, qc = lane & 3;

    // stage weights once (tf32-rounded)
    for (int idx = tid; idx < 128 * 100; idx += 256) {
        int n = idx / 100, k = idx - n * 100;
        W1t[k * SW + n] = tf32r(w1[idx]);
    }
    for (int idx = tid; idx < 4 * 128; idx += 256) {
        int k = 100 + (idx >> 7), n = idx & 127;
        W1t[k * SW + n] = 0.f;
    }
    for (int idx = tid; idx < 128 * 128; idx += 256) {
        int n = idx >> 7, k = idx & 127;
        W2t[k * SW + n] = tf32r(w2[idx]);
    }
    if (tid < 128) { b1s[tid] = b1[tid]; b2s[tid] = b2[tid]; }

    const uint32_t* HAu  = reinterpret_cast<const uint32_t*>(HA);
    const uint32_t* W1u  = reinterpret_cast<const uint32_t*>(W1t);
    const uint32_t* W2u  = reinterpret_cast<const uint32_t*>(W2t);

    int ntiles = (E + 127) >> 7;
    for (int t = blockIdx.x; t < ntiles; t += gridDim.x) {
        int e0 = t << 7;
        __syncthreads();   // prev tile epilogue finished with HA

        // stage attr tile (tf32) + meta
        for (int idx = tid; idx < 128 * 25; idx += 256) {
            int r = idx / 25, ck = idx - r * 25;
            int e = e0 + r;
            float4 v = make_float4(0.f, 0.f, 0.f, 0.f);
            if (e < E) {
                v = *reinterpret_cast<const float4*>(attr + (size_t)e * G + ck * 4);
                v.x = tf32r(v.x); v.y = tf32r(v.y); v.z = tf32r(v.z); v.w = tf32r(v.w);
            }
            *reinterpret_cast<float4*>(HA + r * SA + ck * 4) = v;
        }
        if (tid < 128) {
            *reinterpret_cast<float4*>(HA + tid * SA + 100) = make_float4(0.f, 0.f, 0.f, 0.f);
            int e = e0 + tid;
            if (e < E) {
                srcs[tid] = eidx[e];
                dsts[tid] = eidx[E + e];
                cs[tid]   = (elen[e] <= 10.0f) ? 1.0f : 0.0f;
            } else { srcs[tid] = 0; dsts[tid] = 0; cs[tid] = 0.f; }
        }
        __syncthreads();

        float acc[2][8][4];
#pragma unroll
        for (int mt = 0; mt < 2; mt++)
#pragma unroll
            for (int nt = 0; nt < 8; nt++)
#pragma unroll
                for (int i = 0; i < 4; i++) acc[mt][nt][i] = 0.f;

        // GEMM1: C1 = attr @ W1^T  (K = 104)
        for (int ks = 0; ks < 13; ks++) {
            int k0 = ks * 8;
            uint32_t bf[8][2];
#pragma unroll
            for (int nt = 0; nt < 8; nt++) {
                int col = wn + nt * 8 + qr;
                bf[nt][0] = W1u[(k0 + qc) * SW + col];
                bf[nt][1] = W1u[(k0 + qc + 4) * SW + col];
            }
#pragma unroll
            for (int mt = 0; mt < 2; mt++) {
                int row = wm + mt * 16 + qr;
                uint32_t af[4];
                af[0] = HAu[row * SA + k0 + qc];
                af[1] = HAu[(row + 8) * SA + k0 + qc];
                af[2] = HAu[row * SA + k0 + 4 + qc];
                af[3] = HAu[(row + 8) * SA + k0 + 4 + qc];
#pragma unroll
                for (int nt = 0; nt < 8; nt++)
                    mma_tf32(acc[mt][nt], af, bf[nt], acc[mt][nt]);
            }
        }
        __syncthreads();   // all reads of attr done

        // H = tf32(ssp(C1 + b1)) -> HA
#pragma unroll
        for (int mt = 0; mt < 2; mt++) {
            int row = wm + mt * 16 + qr;
#pragma unroll
            for (int nt = 0; nt < 8; nt++) {
                int col = wn + nt * 8 + qc * 2;
                float2 lo, hi;
                lo.x = tf32r(ssp_f(acc[mt][nt][0] + b1s[col]));
                lo.y = tf32r(ssp_f(acc[mt][nt][1] + b1s[col + 1]));
                hi.x = tf32r(ssp_f(acc[mt][nt][2] + b1s[col]));
                hi.y = tf32r(ssp_f(acc[mt][nt][3] + b1s[col + 1]));
                *reinterpret_cast<float2*>(HA + row * SA + col) = lo;
                *reinterpret_cast<float2*>(HA + (row + 8) * SA + col) = hi;
            }
        }
        __syncthreads();

#pragma unroll
        for (int mt = 0; mt < 2; mt++)
#pragma unroll
            for (int nt = 0; nt < 8; nt++)
#pragma unroll
                for (int i = 0; i < 4; i++) acc[mt][nt][i] = 0.f;

        // GEMM2: C2 = H @ W2^T  (K = 128)
        for (int ks = 0; ks < 16; ks++) {
            int k0 = ks * 8;
            uint32_t bf[8][2];
#pragma unroll
            for (int nt = 0; nt < 8; nt++) {
                int col = wn + nt * 8 + qr;
                bf[nt][0] = W2u[(k0 + qc) * SW + col];
                bf[nt][1] = W2u[(k0 + qc + 4) * SW + col];
            }
#pragma unroll
            for (int mt = 0; mt < 2; mt++) {
                int row = wm + mt * 16 + qr;
                uint32_t af[4];
                af[0] = HAu[row * SA + k0 + qc];
                af[1] = HAu[(row + 8) * SA + k0 + qc];
                af[2] = HAu[row * SA + k0 + 4 + qc];
                af[3] = HAu[(row + 8) * SA + k0 + 4 + qc];
#pragma unroll
                for (int nt = 0; nt < 8; nt++)
                    mma_tf32(acc[mt][nt], af, bf[nt], acc[mt][nt]);
            }
        }
        __syncthreads();   // all reads of H done

        // Wf = (C2 + b2) * C -> HA
#pragma unroll
        for (int mt = 0; mt < 2; mt++) {
            int row = wm + mt * 16 + qr;
            float c0 = cs[row], c1 = cs[row + 8];
#pragma unroll
            for (int nt = 0; nt < 8; nt++) {
                int col = wn + nt * 8 + qc * 2;
                float2 lo, hi;
                lo.x = (acc[mt][nt][0] + b2s[col])     * c0;
                lo.y = (acc[mt][nt][1] + b2s[col + 1]) * c0;
                hi.x = (acc[mt][nt][2] + b2s[col])     * c1;
                hi.y = (acc[mt][nt][3] + b2s[col + 1]) * c1;
                *reinterpret_cast<float2*>(HA + row * SA + col) = lo;
                *reinterpret_cast<float2*>(HA + (row + 8) * SA + col) = hi;
            }
        }
        __syncthreads();

        // epilogue: m_ij = xf[src] * Wf; red-add into m_i[dst]
        {
            int row = tid >> 1, half = tid & 1;
            int e = e0 + row;
            if (e < E) {
                int src = srcs[row], dst = dsts[row];
                const float4* xp = reinterpret_cast<const float4*>(
                    g_xf + (size_t)src * D + half * 64);
                float* mp = g_mi + (size_t)dst * D + half * 64;
                const float* wf = HA + row * SA + half * 64;
#pragma unroll
                for (int i = 0; i < 16; i++) {
                    float4 w = *reinterpret_cast<const float4*>(wf + i * 4);
                    float4 x = xp[i];
                    float rx = w.x * x.x, ry = w.y * x.y;
                    float rz = w.z * x.z, rw = w.w * x.w;
                    asm volatile("red.global.add.v4.f32 [%0], {%1,%2,%3,%4};"
                                 :: "l"(mp + i * 4), "f"(rx), "f"(ry),
                                    "f"(rz), "f"(rw) : "memory");
                }
            }
        }
    }
}

// ---------------- fused update ----------------
__global__ void update_kernel(const float* __restrict__ lin2w,
                              const float* __restrict__ lin2b,
                              const float* __restrict__ linw,
                              const float* __restrict__ linb,
                              int N, float* __restrict__ hout) {
    float* smem = reinterpret_cast<float*>(dynsmem);
    float* l2t = smem;
    float* lat = l2t + D * D;
    float* lbt = lat + D * D;
    float* b2s = lbt + D * D;
    float* bls = b2s + D;
    float* hsm = bls + D;
    float* msm = hsm + 32 * D;
    int tid = threadIdx.x;

    for (int idx = tid; idx < D * D; idx += 256) {
        int d = idx >> 7, k = idx & 127;
        l2t[k * D + d] = lin2w[idx];
    }
    for (int idx = tid; idx < D * 2 * D; idx += 256) {
        int d = idx >> 8, c = idx & 255;
        float v = linw[idx];
        if (c < D) lat[c * D + d] = v;
        else       lbt[(c - D) * D + d] = v;
    }
    if (tid < D) { b2s[tid] = lin2b[tid]; bls[tid] = linb[tid]; }

    int tx = tid & 31, ty = tid >> 5;
    int ntiles = (N + 31) >> 5;
    for (int t = blockIdx.x; t < ntiles; t += gridDim.x) {
        int r0 = t << 5;
        __syncthreads();
        for (int idx = tid; idx < 32 * D; idx += 256) {
            int r = r0 + (idx >> 7);
            hsm[idx] = (r < N) ? g_h[r * D + (idx & 127)] : 0.f;
            msm[idx] = (r < N) ? g_mi[r * D + (idx & 127)] : 0.f;
        }
        __syncthreads();

        float4 a[4];
#pragma unroll
        for (int j = 0; j < 4; j++) a[j] = make_float4(0.f, 0.f, 0.f, 0.f);
#pragma unroll 4
        for (int k = 0; k < D; k++) {
            float4 w = *reinterpret_cast<const float4*>(&l2t[k * D + tx * 4]);
#pragma unroll
            for (int j = 0; j < 4; j++) {
                float v = msm[(ty * 4 + j) * D + k];
                a[j].x += v * w.x; a[j].y += v * w.y;
                a[j].z += v * w.z; a[j].w += v * w.w;
            }
        }
        float4 b2v = *reinterpret_cast<const float4*>(&b2s[tx * 4]);
        float4 mval[4];
#pragma unroll
        for (int j = 0; j < 4; j++) {
            mval[j].x = ssp_f(a[j].x + b2v.x);
            mval[j].y = ssp_f(a[j].y + b2v.y);
            mval[j].z = ssp_f(a[j].z + b2v.z);
            mval[j].w = ssp_f(a[j].w + b2v.w);
        }
        __syncthreads();
#pragma unroll
        for (int j = 0; j < 4; j++)
            *reinterpret_cast<float4*>(&msm[(ty * 4 + j) * D + tx * 4]) = mval[j];
        __syncthreads();

        float4 o[4];
        float4 blv = *reinterpret_cast<const float4*>(&bls[tx * 4]);
#pragma unroll
        for (int j = 0; j < 4; j++) {
            float4 h0 = *reinterpret_cast<const float4*>(
                &hsm[(ty * 4 + j) * D + tx * 4]);
            o[j].x = h0.x + blv.x; o[j].y = h0.y + blv.y;
            o[j].z = h0.z + blv.z; o[j].w = h0.w + blv.w;
        }
#pragma unroll 4
        for (int k = 0; k < D; k++) {
            float4 wa = *reinterpret_cast<const float4*>(&lat[k * D + tx * 4]);
            float4 wb = *reinterpret_cast<const float4*>(&lbt[k * D + tx * 4]);
#pragma unroll
            for (int j = 0; j < 4; j++) {
                float hv = hsm[(ty * 4 + j) * D + k];
                float mv = msm[(ty * 4 + j) * D + k];
                o[j].x += hv * wa.x + mv * wb.x;
                o[j].y += hv * wa.y + mv * wb.y;
                o[j].z += hv * wa.z + mv * wb.z;
                o[j].w += hv * wa.w + mv * wb.w;
            }
        }
        float* outp = hout ? hout : g_h;
#pragma unroll
        for (int j = 0; j < 4; j++) {
            int r = r0 + ty * 4 + j;
            if (r < N)
                *reinterpret_cast<float4*>(&outp[r * D + tx * 4]) = o[j];
        }
    }
}

// ---------------- launch ----------------
extern "C" void kernel_launch(void* const* d_in, const int* in_sizes, int n_in,
                              void* d_out, int out_size) {
    const float* z    = (const float*)d_in[0];
    const int*   eidx = (const int*)d_in[1];
    const float* elen = (const float*)d_in[2];
    const float* attr = (const float*)d_in[3];
    const float* embw = (const float*)d_in[4];
    const float* embb = (const float*)d_in[5];
    const float* w1   = (const float*)d_in[6];
    const float* b1   = (const float*)d_in[7];
    const float* w2   = (const float*)d_in[8];
    const float* b2   = (const float*)d_in[9];
    const float* l1w  = (const float*)d_in[10];
    const float* l2w  = (const float*)d_in[11];
    const float* l2b  = (const float*)d_in[12];
    const float* lw   = (const float*)d_in[13];
    const float* lb   = (const float*)d_in[14];

    int N = in_sizes[0] / ZDIM;
    int E = in_sizes[2];

    const int XF_SMEM  = (D * D + 64 * D) * 4;
    const int UPD_SMEM = (3 * D * D + 2 * D + 64 * D) * 4;

    cudaFuncSetAttribute(xf_kernel,     cudaFuncAttributeMaxDynamicSharedMemorySize, XF_SMEM);
    cudaFuncSetAttribute(edge_kernel,   cudaFuncAttributeMaxDynamicSharedMemorySize, EDGE_SMEM);
    cudaFuncSetAttribute(update_kernel, cudaFuncAttributeMaxDynamicSharedMemorySize, UPD_SMEM);

    int nsm = 148;
    cudaDeviceGetAttribute(&nsm, cudaDevAttrMultiProcessorCount, 0);

    int etiles = (E + 127) >> 7;
    int xtiles = (N + 63) >> 6;
    int utiles = (N + 31) >> 5;
    int gx = 2 * nsm < xtiles ? 2 * nsm : xtiles;
    int ge = nsm < etiles ? nsm : etiles;
    int gu = nsm < utiles ? nsm : utiles;

    embed_kernel<<<(N * D + 255) / 256, 256>>>(z, embw, embb, N);

    for (int l = 0; l < NLAYERS; l++) {
        xf_kernel<<<gx, 256, XF_SMEM>>>(l1w + (size_t)l * D * D, N);
        edge_kernel<<<ge, 256, EDGE_SMEM>>>(attr, eidx, elen,
                                            w1 + (size_t)l * D * G, b1 + (size_t)l * D,
                                            w2 + (size_t)l * D * D, b2 + (size_t)l * D, E);
        float* hout = (l == NLAYERS - 1) ? (float*)d_out : nullptr;
        update_kernel<<<gu, 256, UPD_SMEM>>>(l2w + (size_t)l * D * D, l2b + (size_t)l * D,
                                             lw + (size_t)l * D * 2 * D, lb + (size_t)l * D,
                                             N, hout);
    }
}

// round 8
// speedup vs baseline: 1.7006x; 1.0788x over previous
#include <cuda_runtime.h>
#include <cstdint>
#include <math.h>

#define D 128
#define G 100
#define NLAYERS 6
#define ZDIM 133
#define IND 5
#define NMAX 20000
#define EMAX 320000
#define LOG2F_ 0.6931471805599453f

extern __shared__ char dynsmem[];

// ---------------- scratch ----------------
__device__ __align__(256) float g_h [NMAX * D];
__device__ __align__(256) float g_xf[NMAX * D];
__device__ __align__(256) float g_mi[NMAX * D];

__device__ __forceinline__ float ssp_f(float x) {
    float sp = (x > 15.0f) ? x : log1pf(__expf(x));
    return sp - LOG2F_;
}

__device__ __forceinline__ float tf32r(float x) {
    asm("cvt.rna.tf32.f32 %0, %1;" : "=f"(x) : "f"(x));
    return x;
}

// D = A(16x8) * B(8x8) + C,  tf32 operands, f32 accum
__device__ __forceinline__ void mma_tf32(float* d, const uint32_t* a,
                                         const uint32_t* b, const float* c) {
    asm volatile(
        "mma.sync.aligned.m16n8k8.row.col.f32.tf32.tf32.f32 "
        "{%0,%1,%2,%3}, {%4,%5,%6,%7}, {%8,%9}, {%10,%11,%12,%13};"
        : "=f"(d[0]), "=f"(d[1]), "=f"(d[2]), "=f"(d[3])
        : "r"(a[0]), "r"(a[1]), "r"(a[2]), "r"(a[3]),
          "r"(b[0]), "r"(b[1]),
          "f"(c[0]), "f"(c[1]), "f"(c[2]), "f"(c[3]));
}

// ---------------- embed ----------------
__global__ void embed_kernel(const float* __restrict__ z,
                             const float* __restrict__ w,
                             const float* __restrict__ b, int N) {
    int gid = blockIdx.x * blockDim.x + threadIdx.x;
    if (gid >= N * D) return;
    int i = gid >> 7, d = gid & 127;
    const float* zr = z + (size_t)i * ZDIM;
    float acc = b[d] + zr[IND + d];
#pragma unroll
    for (int k = 0; k < IND; k++) acc += zr[k] * w[d * IND + k];
    g_h[gid] = acc;
}

// ---------------- xf = h @ lin1^T ; zero m_i ----------------
__global__ void xf_kernel(const float* __restrict__ lin1, int N) {
    float* smem = reinterpret_cast<float*>(dynsmem);
    float* wt = smem;
    float* hs = wt + D * D;
    int tid = threadIdx.x;
    for (int idx = tid; idx < D * D; idx += 256) {
        int d = idx >> 7, k = idx & 127;
        wt[k * D + d] = lin1[idx];
    }
    int tx = tid & 31, ty = tid >> 5;
    int ntiles = (N + 63) >> 6;
    for (int t = blockIdx.x; t < ntiles; t += gridDim.x) {
        int r0 = t << 6;
        __syncthreads();
        for (int idx = tid; idx < 64 * D; idx += 256) {
            int r = r0 + (idx >> 7);
            hs[idx] = (r < N) ? g_h[r * D + (idx & 127)] : 0.f;
        }
        for (int idx = tid; idx < 64 * 32; idx += 256) {
            int r = r0 + (idx >> 5);
            if (r < N)
                reinterpret_cast<float4*>(g_mi)[r * 32 + (idx & 31)] =
                    make_float4(0.f, 0.f, 0.f, 0.f);
        }
        __syncthreads();
        float4 acc[8];
#pragma unroll
        for (int j = 0; j < 8; j++) acc[j] = make_float4(0.f, 0.f, 0.f, 0.f);
#pragma unroll 4
        for (int k = 0; k < D; k++) {
            float4 w = *reinterpret_cast<const float4*>(&wt[k * D + tx * 4]);
#pragma unroll
            for (int j = 0; j < 8; j++) {
                float a = hs[(ty * 8 + j) * D + k];
                acc[j].x += a * w.x; acc[j].y += a * w.y;
                acc[j].z += a * w.z; acc[j].w += a * w.w;
            }
        }
#pragma unroll
        for (int j = 0; j < 8; j++) {
            int r = r0 + ty * 8 + j;
            if (r < N)
                *reinterpret_cast<float4*>(&g_xf[r * D + tx * 4]) = acc[j];
        }
    }
}

// ---------------- tf32 mma.sync edge kernel (512 threads, 16 warps) ----------------
// smem (floats):
//   HA  [128][132]   attr / hidden / Wf (reused)      16896
//   W1t [104][136]   (k-major, padded K 100->104)     14144
//   W2t [128][136]                                    17408
//   b1s[128] b2s[128] srcs[128] dsts[128] cs[128]       640
//   total 49088 floats = 196352 bytes
#define SA 132
#define SW 136
#define OFF_W1 16896
#define OFF_W2 31040
#define OFF_B1 48448
#define OFF_B2 48576
#define OFF_SRC 48704
#define OFF_DST 48832
#define OFF_CS  48960
#define EDGE_SMEM (49088 * 4)
#define ETHREADS 512

__global__ __launch_bounds__(ETHREADS, 1)
void edge_kernel(const float* __restrict__ attr,
                 const int* __restrict__ eidx,
                 const float* __restrict__ elen,
                 const float* __restrict__ w1,
                 const float* __restrict__ b1,
                 const float* __restrict__ w2,
                 const float* __restrict__ b2, int E) {
    float* sm  = reinterpret_cast<float*>(dynsmem);
    float* HA  = sm;
    float* W1t = sm + OFF_W1;
    float* W2t = sm + OFF_W2;
    float* b1s = sm + OFF_B1;
    float* b2s = sm + OFF_B2;
    int*   srcs = reinterpret_cast<int*>(sm + OFF_SRC);
    int*   dsts = reinterpret_cast<int*>(sm + OFF_DST);
    float* cs   = sm + OFF_CS;

    int tid = threadIdx.x, lane = tid & 31, wid = tid >> 5;
    int wm = (wid & 7) * 16;       // row base of this warp's 16x64 tile
    int wn = (wid >> 3) * 64;      // col base
    int qr = lane >> 2, qc = lane & 3;

    // stage weights once (tf32-rounded)
    for (int idx = tid; idx < 128 * 100; idx += ETHREADS) {
        int n = idx / 100, k = idx - n * 100;
        W1t[k * SW + n] = tf32r(w1[idx]);
    }
    {   // zero-pad W1t rows k=100..103 (512 threads -> exactly one pass)
        int k = 100 + (tid >> 7), n = tid & 127;
        W1t[k * SW + n] = 0.f;
    }
    for (int idx = tid; idx < 128 * 128; idx += ETHREADS) {
        int n = idx >> 7, k = idx & 127;
        W2t[k * SW + n] = tf32r(w2[idx]);
    }
    if (tid < 128) { b1s[tid] = b1[tid]; b2s[tid] = b2[tid]; }

    const uint32_t* HAu  = reinterpret_cast<const uint32_t*>(HA);
    const uint32_t* W1u  = reinterpret_cast<const uint32_t*>(W1t);
    const uint32_t* W2u  = reinterpret_cast<const uint32_t*>(W2t);

    int ntiles = (E + 127) >> 7;
    for (int t = blockIdx.x; t < ntiles; t += gridDim.x) {
        int e0 = t << 7;
        __syncthreads();   // prev tile epilogue finished with HA

        // stage attr tile (tf32) + meta
        for (int idx = tid; idx < 128 * 25; idx += ETHREADS) {
            int r = idx / 25, ck = idx - r * 25;
            int e = e0 + r;
            float4 v = make_float4(0.f, 0.f, 0.f, 0.f);
            if (e < E) {
                v = *reinterpret_cast<const float4*>(attr + (size_t)e * G + ck * 4);
                v.x = tf32r(v.x); v.y = tf32r(v.y); v.z = tf32r(v.z); v.w = tf32r(v.w);
            }
            *reinterpret_cast<float4*>(HA + r * SA + ck * 4) = v;
        }
        if (tid < 128) {
            *reinterpret_cast<float4*>(HA + tid * SA + 100) = make_float4(0.f, 0.f, 0.f, 0.f);
            int e = e0 + tid;
            if (e < E) {
                srcs[tid] = eidx[e];
                dsts[tid] = eidx[E + e];
                cs[tid]   = (elen[e] <= 10.0f) ? 1.0f : 0.0f;
            } else { srcs[tid] = 0; dsts[tid] = 0; cs[tid] = 0.f; }
        }
        __syncthreads();

        float acc[8][4];
#pragma unroll
        for (int nt = 0; nt < 8; nt++)
#pragma unroll
            for (int i = 0; i < 4; i++) acc[nt][i] = 0.f;

        // GEMM1: C1 = attr @ W1^T  (K = 104)
        for (int ks = 0; ks < 13; ks++) {
            int k0 = ks * 8;
            int row = wm + qr;
            uint32_t af[4];
            af[0] = HAu[row * SA + k0 + qc];
            af[1] = HAu[(row + 8) * SA + k0 + qc];
            af[2] = HAu[row * SA + k0 + 4 + qc];
            af[3] = HAu[(row + 8) * SA + k0 + 4 + qc];
#pragma unroll
            for (int nt = 0; nt < 8; nt++) {
                int col = wn + nt * 8 + qr;
                uint32_t bf[2];
                bf[0] = W1u[(k0 + qc) * SW + col];
                bf[1] = W1u[(k0 + qc + 4) * SW + col];
                mma_tf32(acc[nt], af, bf, acc[nt]);
            }
        }
        __syncthreads();   // all reads of attr done

        // H = tf32(ssp(C1 + b1)) -> HA
        {
            int row = wm + qr;
#pragma unroll
            for (int nt = 0; nt < 8; nt++) {
                int col = wn + nt * 8 + qc * 2;
                float2 lo, hi;
                lo.x = tf32r(ssp_f(acc[nt][0] + b1s[col]));
                lo.y = tf32r(ssp_f(acc[nt][1] + b1s[col + 1]));
                hi.x = tf32r(ssp_f(acc[nt][2] + b1s[col]));
                hi.y = tf32r(ssp_f(acc[nt][3] + b1s[col + 1]));
                *reinterpret_cast<float2*>(HA + row * SA + col) = lo;
                *reinterpret_cast<float2*>(HA + (row + 8) * SA + col) = hi;
            }
        }
        __syncthreads();

#pragma unroll
        for (int nt = 0; nt < 8; nt++)
#pragma unroll
            for (int i = 0; i < 4; i++) acc[nt][i] = 0.f;

        // GEMM2: C2 = H @ W2^T  (K = 128)
        for (int ks = 0; ks < 16; ks++) {
            int k0 = ks * 8;
            int row = wm + qr;
            uint32_t af[4];
            af[0] = HAu[row * SA + k0 + qc];
            af[1] = HAu[(row + 8) * SA + k0 + qc];
            af[2] = HAu[row * SA + k0 + 4 + qc];
            af[3] = HAu[(row + 8) * SA + k0 + 4 + qc];
#pragma unroll
            for (int nt = 0; nt < 8; nt++) {
                int col = wn + nt * 8 + qr;
                uint32_t bf[2];
                bf[0] = W2u[(k0 + qc) * SW + col];
                bf[1] = W2u[(k0 + qc + 4) * SW + col];
                mma_tf32(acc[nt], af, bf, acc[nt]);
            }
        }
        __syncthreads();   // all reads of H done

        // Wf = (C2 + b2) * C -> HA
        {
            int row = wm + qr;
            float c0 = cs[row], c1 = cs[row + 8];
#pragma unroll
            for (int nt = 0; nt < 8; nt++) {
                int col = wn + nt * 8 + qc * 2;
                float2 lo, hi;
                lo.x = (acc[nt][0] + b2s[col])     * c0;
                lo.y = (acc[nt][1] + b2s[col + 1]) * c0;
                hi.x = (acc[nt][2] + b2s[col])     * c1;
                hi.y = (acc[nt][3] + b2s[col + 1]) * c1;
                *reinterpret_cast<float2*>(HA + row * SA + col) = lo;
                *reinterpret_cast<float2*>(HA + (row + 8) * SA + col) = hi;
            }
        }
        __syncthreads();

        // epilogue: m_ij = xf[src] * Wf; red-add into m_i[dst]
        // 512 threads: 4 threads per row, each handles a 32-float quarter
        {
            int row = tid >> 2, q = tid & 3;
            int e = e0 + row;
            if (e < E) {
                int src = srcs[row], dst = dsts[row];
                const float4* xp = reinterpret_cast<const float4*>(
                    g_xf + (size_t)src * D + q * 32);
                float* mp = g_mi + (size_t)dst * D + q * 32;
                const float* wf = HA + row * SA + q * 32;
#pragma unroll
                for (int i = 0; i < 8; i++) {
                    float4 w = *reinterpret_cast<const float4*>(wf + i * 4);
                    float4 x = xp[i];
                    float rx = w.x * x.x, ry = w.y * x.y;
                    float rz = w.z * x.z, rw = w.w * x.w;
                    asm volatile("red.global.add.v4.f32 [%0], {%1,%2,%3,%4};"
                                 :: "l"(mp + i * 4), "f"(rx), "f"(ry),
                                    "f"(rz), "f"(rw) : "memory");
                }
            }
        }
    }
}

// ---------------- fused update ----------------
__global__ void update_kernel(const float* __restrict__ lin2w,
                              const float* __restrict__ lin2b,
                              const float* __restrict__ linw,
                              const float* __restrict__ linb,
                              int N, float* __restrict__ hout) {
    float* smem = reinterpret_cast<float*>(dynsmem);
    float* l2t = smem;
    float* lat = l2t + D * D;
    float* lbt = lat + D * D;
    float* b2s = lbt + D * D;
    float* bls = b2s + D;
    float* hsm = bls + D;
    float* msm = hsm + 32 * D;
    int tid = threadIdx.x;

    for (int idx = tid; idx < D * D; idx += 256) {
        int d = idx >> 7, k = idx & 127;
        l2t[k * D + d] = lin2w[idx];
    }
    for (int idx = tid; idx < D * 2 * D; idx += 256) {
        int d = idx >> 8, c = idx & 255;
        float v = linw[idx];
        if (c < D) lat[c * D + d] = v;
        else       lbt[(c - D) * D + d] = v;
    }
    if (tid < D) { b2s[tid] = lin2b[tid]; bls[tid] = linb[tid]; }

    int tx = tid & 31, ty = tid >> 5;
    int ntiles = (N + 31) >> 5;
    for (int t = blockIdx.x; t < ntiles; t += gridDim.x) {
        int r0 = t << 5;
        __syncthreads();
        for (int idx = tid; idx < 32 * D; idx += 256) {
            int r = r0 + (idx >> 7);
            hsm[idx] = (r < N) ? g_h[r * D + (idx & 127)] : 0.f;
            msm[idx] = (r < N) ? g_mi[r * D + (idx & 127)] : 0.f;
        }
        __syncthreads();

        float4 a[4];
#pragma unroll
        for (int j = 0; j < 4; j++) a[j] = make_float4(0.f, 0.f, 0.f, 0.f);
#pragma unroll 4
        for (int k = 0; k < D; k++) {
            float4 w = *reinterpret_cast<const float4*>(&l2t[k * D + tx * 4]);
#pragma unroll
            for (int j = 0; j < 4; j++) {
                float v = msm[(ty * 4 + j) * D + k];
                a[j].x += v * w.x; a[j].y += v * w.y;
                a[j].z += v * w.z; a[j].w += v * w.w;
            }
        }
        float4 b2v = *reinterpret_cast<const float4*>(&b2s[tx * 4]);
        float4 mval[4];
#pragma unroll
        for (int j = 0; j < 4; j++) {
            mval[j].x = ssp_f(a[j].x + b2v.x);
            mval[j].y = ssp_f(a[j].y + b2v.y);
            mval[j].z = ssp_f(a[j].z + b2v.z);
            mval[j].w = ssp_f(a[j].w + b2v.w);
        }
        __syncthreads();
#pragma unroll
        for (int j = 0; j < 4; j++)
            *reinterpret_cast<float4*>(&msm[(ty * 4 + j) * D + tx * 4]) = mval[j];
        __syncthreads();

        float4 o[4];
        float4 blv = *reinterpret_cast<const float4*>(&bls[tx * 4]);
#pragma unroll
        for (int j = 0; j < 4; j++) {
            float4 h0 = *reinterpret_cast<const float4*>(
                &hsm[(ty * 4 + j) * D + tx * 4]);
            o[j].x = h0.x + blv.x; o[j].y = h0.y + blv.y;
            o[j].z = h0.z + blv.z; o[j].w = h0.w + blv.w;
        }
#pragma unroll 4
        for (int k = 0; k < D; k++) {
            float4 wa = *reinterpret_cast<const float4*>(&lat[k * D + tx * 4]);
            float4 wb = *reinterpret_cast<const float4*>(&lbt[k * D + tx * 4]);
#pragma unroll
            for (int j = 0; j < 4; j++) {
                float hv = hsm[(ty * 4 + j) * D + k];
                float mv = msm[(ty * 4 + j) * D + k];
                o[j].x += hv * wa.x + mv * wb.x;
                o[j].y += hv * wa.y + mv * wb.y;
                o[j].z += hv * wa.z + mv * wb.z;
                o[j].w += hv * wa.w + mv * wb.w;
            }
        }
        float* outp = hout ? hout : g_h;
#pragma unroll
        for (int j = 0; j < 4; j++) {
            int r = r0 + ty * 4 + j;
            if (r < N)
                *reinterpret_cast<float4*>(&outp[r * D + tx * 4]) = o[j];
        }
    }
}

// ---------------- launch ----------------
extern "C" void kernel_launch(void* const* d_in, const int* in_sizes, int n_in,
                              void* d_out, int out_size) {
    const float* z    = (const float*)d_in[0];
    const int*   eidx = (const int*)d_in[1];
    const float* elen = (const float*)d_in[2];
    const float* attr = (const float*)d_in[3];
    const float* embw = (const float*)d_in[4];
    const float* embb = (const float*)d_in[5];
    const float* w1   = (const float*)d_in[6];
    const float* b1   = (const float*)d_in[7];
    const float* w2   = (const float*)d_in[8];
    const float* b2   = (const float*)d_in[9];
    const float* l1w  = (const float*)d_in[10];
    const float* l2w  = (const float*)d_in[11];
    const float* l2b  = (const float*)d_in[12];
    const float* lw   = (const float*)d_in[13];
    const float* lb   = (const float*)d_in[14];

    int N = in_sizes[0] / ZDIM;
    int E = in_sizes[2];

    const int XF_SMEM  = (D * D + 64 * D) * 4;
    const int UPD_SMEM = (3 * D * D + 2 * D + 64 * D) * 4;

    cudaFuncSetAttribute(xf_kernel,     cudaFuncAttributeMaxDynamicSharedMemorySize, XF_SMEM);
    cudaFuncSetAttribute(edge_kernel,   cudaFuncAttributeMaxDynamicSharedMemorySize, EDGE_SMEM);
    cudaFuncSetAttribute(update_kernel, cudaFuncAttributeMaxDynamicSharedMemorySize, UPD_SMEM);

    int nsm = 148;
    cudaDeviceGetAttribute(&nsm, cudaDevAttrMultiProcessorCount, 0);

    int etiles = (E + 127) >> 7;
    int xtiles = (N + 63) >> 6;
    int utiles = (N + 31) >> 5;
    int gx = 2 * nsm < xtiles ? 2 * nsm : xtiles;
    int ge = nsm < etiles ? nsm : etiles;
    int gu = nsm < utiles ? nsm : utiles;

    embed_kernel<<<(N * D + 255) / 256, 256>>>(z, embw, embb, N);

    for (int l = 0; l < NLAYERS; l++) {
        xf_kernel<<<gx, 256, XF_SMEM>>>(l1w + (size_t)l * D * D, N);
        edge_kernel<<<ge, ETHREADS, EDGE_SMEM>>>(attr, eidx, elen,
                                            w1 + (size_t)l * D * G, b1 + (size_t)l * D,
                                            w2 + (size_t)l * D * D, b2 + (size_t)l * D, E);
        float* hout = (l == NLAYERS - 1) ? (float*)d_out : nullptr;
        update_kernel<<<gu, 256, UPD_SMEM>>>(l2w + (size_t)l * D * D, l2b + (size_t)l * D,
                                             lw + (size_t)l * D * 2 * D, lb + (size_t)l * D,
                                             N, hout);
    }
}

// round 9
// speedup vs baseline: 1.7743x; 1.0433x over previous
#include <cuda_runtime.h>
#include <cstdint>
#include <math.h>

#define D 128
#define G 100
#define NLAYERS 6
#define ZDIM 133
#define IND 5
#define NMAX 20000
#define EMAX 320000
#define LOG2F_ 0.6931471805599453f

extern __shared__ char dynsmem[];

// ---------------- scratch ----------------
__device__ __align__(256) float g_h [NMAX * D];
__device__ __align__(256) float g_xf[NMAX * D];
__device__ __align__(256) float g_mi[NMAX * D];

__device__ __forceinline__ float ssp_f(float x) {
    float sp = (x > 15.0f) ? x : log1pf(__expf(x));
    return sp - LOG2F_;
}

__device__ __forceinline__ float tf32r(float x) {
    asm("cvt.rna.tf32.f32 %0, %1;" : "=f"(x) : "f"(x));
    return x;
}

// D = A(16x8) * B(8x8) + C,  tf32 operands, f32 accum
__device__ __forceinline__ void mma_tf32(float* d, const uint32_t* a,
                                         const uint32_t* b, const float* c) {
    asm volatile(
        "mma.sync.aligned.m16n8k8.row.col.f32.tf32.tf32.f32 "
        "{%0,%1,%2,%3}, {%4,%5,%6,%7}, {%8,%9}, {%10,%11,%12,%13};"
        : "=f"(d[0]), "=f"(d[1]), "=f"(d[2]), "=f"(d[3])
        : "r"(a[0]), "r"(a[1]), "r"(a[2]), "r"(a[3]),
          "r"(b[0]), "r"(b[1]),
          "f"(c[0]), "f"(c[1]), "f"(c[2]), "f"(c[3]));
}

// ---------------- embed ----------------
__global__ void embed_kernel(const float* __restrict__ z,
                             const float* __restrict__ w,
                             const float* __restrict__ b, int N) {
    int gid = blockIdx.x * blockDim.x + threadIdx.x;
    if (gid >= N * D) return;
    int i = gid >> 7, d = gid & 127;
    const float* zr = z + (size_t)i * ZDIM;
    float acc = b[d] + zr[IND + d];
#pragma unroll
    for (int k = 0; k < IND; k++) acc += zr[k] * w[d * IND + k];
    g_h[gid] = acc;
}

// ---------------- xf = h @ lin1^T ; zero m_i ----------------
__global__ void xf_kernel(const float* __restrict__ lin1, int N) {
    float* smem = reinterpret_cast<float*>(dynsmem);
    float* wt = smem;
    float* hs = wt + D * D;
    int tid = threadIdx.x;
    for (int idx = tid; idx < D * D; idx += 256) {
        int d = idx >> 7, k = idx & 127;
        wt[k * D + d] = lin1[idx];
    }
    int tx = tid & 31, ty = tid >> 5;
    int ntiles = (N + 63) >> 6;
    for (int t = blockIdx.x; t < ntiles; t += gridDim.x) {
        int r0 = t << 6;
        __syncthreads();
        for (int idx = tid; idx < 64 * D; idx += 256) {
            int r = r0 + (idx >> 7);
            hs[idx] = (r < N) ? g_h[r * D + (idx & 127)] : 0.f;
        }
        for (int idx = tid; idx < 64 * 32; idx += 256) {
            int r = r0 + (idx >> 5);
            if (r < N)
                reinterpret_cast<float4*>(g_mi)[r * 32 + (idx & 31)] =
                    make_float4(0.f, 0.f, 0.f, 0.f);
        }
        __syncthreads();
        float4 acc[8];
#pragma unroll
        for (int j = 0; j < 8; j++) acc[j] = make_float4(0.f, 0.f, 0.f, 0.f);
#pragma unroll 4
        for (int k = 0; k < D; k++) {
            float4 w = *reinterpret_cast<const float4*>(&wt[k * D + tx * 4]);
#pragma unroll
            for (int j = 0; j < 8; j++) {
                float a = hs[(ty * 8 + j) * D + k];
                acc[j].x += a * w.x; acc[j].y += a * w.y;
                acc[j].z += a * w.z; acc[j].w += a * w.w;
            }
        }
#pragma unroll
        for (int j = 0; j < 8; j++) {
            int r = r0 + ty * 8 + j;
            if (r < N)
                *reinterpret_cast<float4*>(&g_xf[r * D + tx * 4]) = acc[j];
        }
    }
}

// ---------------- tf32 mma.sync edge kernel (512 threads, 16 warps) ----------------
#define SA 132
#define SW 136
#define OFF_W1 16896
#define OFF_W2 31040
#define OFF_B1 48448
#define OFF_B2 48576
#define OFF_SRC 48704
#define OFF_DST 48832
#define OFF_CS  48960
#define EDGE_SMEM (49088 * 4)
#define ETHREADS 512

__global__ __launch_bounds__(ETHREADS, 1)
void edge_kernel(const float* __restrict__ attr,
                 const int* __restrict__ eidx,
                 const float* __restrict__ elen,
                 const float* __restrict__ w1,
                 const float* __restrict__ b1,
                 const float* __restrict__ w2,
                 const float* __restrict__ b2, int E) {
    float* sm  = reinterpret_cast<float*>(dynsmem);
    float* HA  = sm;
    float* W1t = sm + OFF_W1;
    float* W2t = sm + OFF_W2;
    float* b1s = sm + OFF_B1;
    float* b2s = sm + OFF_B2;
    int*   srcs = reinterpret_cast<int*>(sm + OFF_SRC);
    int*   dsts = reinterpret_cast<int*>(sm + OFF_DST);
    float* cs   = sm + OFF_CS;

    int tid = threadIdx.x, lane = tid & 31, wid = tid >> 5;
    int wm = (wid & 7) * 16;       // row base of this warp's 16x64 tile
    int wn = (wid >> 3) * 64;      // col base
    int qr = lane >> 2, qc = lane & 3;

    // stage weights once (tf32-rounded)
    for (int idx = tid; idx < 128 * 100; idx += ETHREADS) {
        int n = idx / 100, k = idx - n * 100;
        W1t[k * SW + n] = tf32r(w1[idx]);
    }
    {   // zero-pad W1t rows k=100..103
        int k = 100 + (tid >> 7), n = tid & 127;
        W1t[k * SW + n] = 0.f;
    }
    for (int idx = tid; idx < 128 * 128; idx += ETHREADS) {
        int n = idx >> 7, k = idx & 127;
        W2t[k * SW + n] = tf32r(w2[idx]);
    }
    if (tid < 128) { b1s[tid] = b1[tid]; b2s[tid] = b2[tid]; }

    const uint32_t* HAu  = reinterpret_cast<const uint32_t*>(HA);
    const uint32_t* W1u  = reinterpret_cast<const uint32_t*>(W1t);
    const uint32_t* W2u  = reinterpret_cast<const uint32_t*>(W2t);

    int ntiles = (E + 127) >> 7;
    for (int t = blockIdx.x; t < ntiles; t += gridDim.x) {
        int e0 = t << 7;
        __syncthreads();   // prev tile epilogue finished with HA

        // stage attr tile (tf32) + meta
        for (int idx = tid; idx < 128 * 25; idx += ETHREADS) {
            int r = idx / 25, ck = idx - r * 25;
            int e = e0 + r;
            float4 v = make_float4(0.f, 0.f, 0.f, 0.f);
            if (e < E) {
                v = *reinterpret_cast<const float4*>(attr + (size_t)e * G + ck * 4);
                v.x = tf32r(v.x); v.y = tf32r(v.y); v.z = tf32r(v.z); v.w = tf32r(v.w);
            }
            *reinterpret_cast<float4*>(HA + r * SA + ck * 4) = v;
        }
        if (tid < 128) {
            *reinterpret_cast<float4*>(HA + tid * SA + 100) = make_float4(0.f, 0.f, 0.f, 0.f);
            int e = e0 + tid;
            if (e < E) {
                srcs[tid] = eidx[e];
                dsts[tid] = eidx[E + e];
                cs[tid]   = (elen[e] <= 10.0f) ? 1.0f : 0.0f;
            } else { srcs[tid] = 0; dsts[tid] = 0; cs[tid] = 0.f; }
        }
        __syncthreads();

        float acc[8][4];
#pragma unroll
        for (int nt = 0; nt < 8; nt++)
#pragma unroll
            for (int i = 0; i < 4; i++) acc[nt][i] = 0.f;

        // GEMM1: C1 = attr @ W1^T  (K = 104)
        for (int ks = 0; ks < 13; ks++) {
            int k0 = ks * 8;
            int row = wm + qr;
            uint32_t af[4];
            af[0] = HAu[row * SA + k0 + qc];
            af[1] = HAu[(row + 8) * SA + k0 + qc];
            af[2] = HAu[row * SA + k0 + 4 + qc];
            af[3] = HAu[(row + 8) * SA + k0 + 4 + qc];
#pragma unroll
            for (int nt = 0; nt < 8; nt++) {
                int col = wn + nt * 8 + qr;
                uint32_t bf[2];
                bf[0] = W1u[(k0 + qc) * SW + col];
                bf[1] = W1u[(k0 + qc + 4) * SW + col];
                mma_tf32(acc[nt], af, bf, acc[nt]);
            }
        }
        __syncthreads();   // all reads of attr done

        // H = tf32(ssp(C1 + b1)) -> HA
        {
            int row = wm + qr;
#pragma unroll
            for (int nt = 0; nt < 8; nt++) {
                int col = wn + nt * 8 + qc * 2;
                float2 lo, hi;
                lo.x = tf32r(ssp_f(acc[nt][0] + b1s[col]));
                lo.y = tf32r(ssp_f(acc[nt][1] + b1s[col + 1]));
                hi.x = tf32r(ssp_f(acc[nt][2] + b1s[col]));
                hi.y = tf32r(ssp_f(acc[nt][3] + b1s[col + 1]));
                *reinterpret_cast<float2*>(HA + row * SA + col) = lo;
                *reinterpret_cast<float2*>(HA + (row + 8) * SA + col) = hi;
            }
        }
        __syncthreads();

        // prefetch xf[src] gather for the epilogue — hides L2 latency under GEMM2
        float4 xf_pref[8];
        {
            int prow = tid >> 2, pq = tid & 3;
            int pe = e0 + prow;
            if (pe < E) {
                const float4* pxp = reinterpret_cast<const float4*>(
                    g_xf + (size_t)srcs[prow] * D + pq * 32);
#pragma unroll
                for (int i = 0; i < 8; i++) xf_pref[i] = pxp[i];
            } else {
#pragma unroll
                for (int i = 0; i < 8; i++) xf_pref[i] = make_float4(0.f, 0.f, 0.f, 0.f);
            }
        }

#pragma unroll
        for (int nt = 0; nt < 8; nt++)
#pragma unroll
            for (int i = 0; i < 4; i++) acc[nt][i] = 0.f;

        // GEMM2: C2 = H @ W2^T  (K = 128)
        for (int ks = 0; ks < 16; ks++) {
            int k0 = ks * 8;
            int row = wm + qr;
            uint32_t af[4];
            af[0] = HAu[row * SA + k0 + qc];
            af[1] = HAu[(row + 8) * SA + k0 + qc];
            af[2] = HAu[row * SA + k0 + 4 + qc];
            af[3] = HAu[(row + 8) * SA + k0 + 4 + qc];
#pragma unroll
            for (int nt = 0; nt < 8; nt++) {
                int col = wn + nt * 8 + qr;
                uint32_t bf[2];
                bf[0] = W2u[(k0 + qc) * SW + col];
                bf[1] = W2u[(k0 + qc + 4) * SW + col];
                mma_tf32(acc[nt], af, bf, acc[nt]);
            }
        }
        __syncthreads();   // all reads of H done

        // Wf = (C2 + b2) * C -> HA
        {
            int row = wm + qr;
            float c0 = cs[row], c1 = cs[row + 8];
#pragma unroll
            for (int nt = 0; nt < 8; nt++) {
                int col = wn + nt * 8 + qc * 2;
                float2 lo, hi;
                lo.x = (acc[nt][0] + b2s[col])     * c0;
                lo.y = (acc[nt][1] + b2s[col + 1]) * c0;
                hi.x = (acc[nt][2] + b2s[col])     * c1;
                hi.y = (acc[nt][3] + b2s[col + 1]) * c1;
                *reinterpret_cast<float2*>(HA + row * SA + col) = lo;
                *reinterpret_cast<float2*>(HA + (row + 8) * SA + col) = hi;
            }
        }
        __syncthreads();

        // epilogue: m_ij = xf_pref * Wf; red-add into m_i[dst]
        {
            int row = tid >> 2, q = tid & 3;
            int e = e0 + row;
            if (e < E) {
                int dst = dsts[row];
                float* mp = g_mi + (size_t)dst * D + q * 32;
                const float* wf = HA + row * SA + q * 32;
#pragma unroll
                for (int i = 0; i < 8; i++) {
                    float4 w = *reinterpret_cast<const float4*>(wf + i * 4);
                    float4 x = xf_pref[i];
                    float rx = w.x * x.x, ry = w.y * x.y;
                    float rz = w.z * x.z, rw = w.w * x.w;
                    asm volatile("red.global.add.v4.f32 [%0], {%1,%2,%3,%4};"
                                 :: "l"(mp + i * 4), "f"(rx), "f"(ry),
                                    "f"(rz), "f"(rw) : "memory");
                }
            }
        }
    }
}

// ---------------- fused update (512 threads, 16 warps) ----------------
#define UTHREADS 512
__global__ __launch_bounds__(UTHREADS, 1)
void update_kernel(const float* __restrict__ lin2w,
                   const float* __restrict__ lin2b,
                   const float* __restrict__ linw,
                   const float* __restrict__ linb,
                   int N, float* __restrict__ hout) {
    float* smem = reinterpret_cast<float*>(dynsmem);
    float* l2t = smem;
    float* lat = l2t + D * D;
    float* lbt = lat + D * D;
    float* b2s = lbt + D * D;
    float* bls = b2s + D;
    float* hsm = bls + D;
    float* msm = hsm + 32 * D;
    int tid = threadIdx.x;

    for (int idx = tid; idx < D * D; idx += UTHREADS) {
        int d = idx >> 7, k = idx & 127;
        l2t[k * D + d] = lin2w[idx];
    }
    for (int idx = tid; idx < D * 2 * D; idx += UTHREADS) {
        int d = idx >> 8, c = idx & 255;
        float v = linw[idx];
        if (c < D) lat[c * D + d] = v;
        else       lbt[(c - D) * D + d] = v;
    }
    if (tid < D) { b2s[tid] = lin2b[tid]; bls[tid] = linb[tid]; }

    int tx = tid & 31, ty = tid >> 5;   // 16 warps, 2 rows each
    int ntiles = (N + 31) >> 5;
    for (int t = blockIdx.x; t < ntiles; t += gridDim.x) {
        int r0 = t << 5;
        __syncthreads();
        for (int idx = tid; idx < 32 * D; idx += UTHREADS) {
            int r = r0 + (idx >> 7);
            hsm[idx] = (r < N) ? g_h[r * D + (idx & 127)] : 0.f;
            msm[idx] = (r < N) ? g_mi[r * D + (idx & 127)] : 0.f;
        }
        __syncthreads();

        // phase 1: m tile (2 rows x 4 cols per thread)
        float4 a[2];
#pragma unroll
        for (int j = 0; j < 2; j++) a[j] = make_float4(0.f, 0.f, 0.f, 0.f);
#pragma unroll 4
        for (int k = 0; k < D; k++) {
            float4 w = *reinterpret_cast<const float4*>(&l2t[k * D + tx * 4]);
#pragma unroll
            for (int j = 0; j < 2; j++) {
                float v = msm[(ty * 2 + j) * D + k];
                a[j].x += v * w.x; a[j].y += v * w.y;
                a[j].z += v * w.z; a[j].w += v * w.w;
            }
        }
        float4 b2v = *reinterpret_cast<const float4*>(&b2s[tx * 4]);
        float4 mval[2];
#pragma unroll
        for (int j = 0; j < 2; j++) {
            mval[j].x = ssp_f(a[j].x + b2v.x);
            mval[j].y = ssp_f(a[j].y + b2v.y);
            mval[j].z = ssp_f(a[j].z + b2v.z);
            mval[j].w = ssp_f(a[j].w + b2v.w);
        }
        __syncthreads();   // all reads of mi done
#pragma unroll
        for (int j = 0; j < 2; j++)
            *reinterpret_cast<float4*>(&msm[(ty * 2 + j) * D + tx * 4]) = mval[j];
        __syncthreads();

        // phase 2: out = h + h@lwA^T + m@lwB^T + lin_b
        float4 o[2];
        float4 blv = *reinterpret_cast<const float4*>(&bls[tx * 4]);
#pragma unroll
        for (int j = 0; j < 2; j++) {
            float4 h0 = *reinterpret_cast<const float4*>(
                &hsm[(ty * 2 + j) * D + tx * 4]);
            o[j].x = h0.x + blv.x; o[j].y = h0.y + blv.y;
            o[j].z = h0.z + blv.z; o[j].w = h0.w + blv.w;
        }
#pragma unroll 4
        for (int k = 0; k < D; k++) {
            float4 wa = *reinterpret_cast<const float4*>(&lat[k * D + tx * 4]);
            float4 wb = *reinterpret_cast<const float4*>(&lbt[k * D + tx * 4]);
#pragma unroll
            for (int j = 0; j < 2; j++) {
                float hv = hsm[(ty * 2 + j) * D + k];
                float mv = msm[(ty * 2 + j) * D + k];
                o[j].x += hv * wa.x + mv * wb.x;
                o[j].y += hv * wa.y + mv * wb.y;
                o[j].z += hv * wa.z + mv * wb.z;
                o[j].w += hv * wa.w + mv * wb.w;
            }
        }
        float* outp = hout ? hout : g_h;
#pragma unroll
        for (int j = 0; j < 2; j++) {
            int r = r0 + ty * 2 + j;
            if (r < N)
                *reinterpret_cast<float4*>(&outp[r * D + tx * 4]) = o[j];
        }
    }
}

// ---------------- launch ----------------
extern "C" void kernel_launch(void* const* d_in, const int* in_sizes, int n_in,
                              void* d_out, int out_size) {
    const float* z    = (const float*)d_in[0];
    const int*   eidx = (const int*)d_in[1];
    const float* elen = (const float*)d_in[2];
    const float* attr = (const float*)d_in[3];
    const float* embw = (const float*)d_in[4];
    const float* embb = (const float*)d_in[5];
    const float* w1   = (const float*)d_in[6];
    const float* b1   = (const float*)d_in[7];
    const float* w2   = (const float*)d_in[8];
    const float* b2   = (const float*)d_in[9];
    const float* l1w  = (const float*)d_in[10];
    const float* l2w  = (const float*)d_in[11];
    const float* l2b  = (const float*)d_in[12];
    const float* lw   = (const float*)d_in[13];
    const float* lb   = (const float*)d_in[14];

    int N = in_sizes[0] / ZDIM;
    int E = in_sizes[2];

    const int XF_SMEM  = (D * D + 64 * D) * 4;
    const int UPD_SMEM = (3 * D * D + 2 * D + 64 * D) * 4;

    cudaFuncSetAttribute(xf_kernel,     cudaFuncAttributeMaxDynamicSharedMemorySize, XF_SMEM);
    cudaFuncSetAttribute(edge_kernel,   cudaFuncAttributeMaxDynamicSharedMemorySize, EDGE_SMEM);
    cudaFuncSetAttribute(update_kernel, cudaFuncAttributeMaxDynamicSharedMemorySize, UPD_SMEM);

    int nsm = 148;
    cudaDeviceGetAttribute(&nsm, cudaDevAttrMultiProcessorCount, 0);

    int etiles = (E + 127) >> 7;
    int xtiles = (N + 63) >> 6;
    int utiles = (N + 31) >> 5;
    int gx = 2 * nsm < xtiles ? 2 * nsm : xtiles;
    int ge = nsm < etiles ? nsm : etiles;
    int gu = nsm < utiles ? nsm : utiles;

    embed_kernel<<<(N * D + 255) / 256, 256>>>(z, embw, embb, N);

    for (int l = 0; l < NLAYERS; l++) {
        xf_kernel<<<gx, 256, XF_SMEM>>>(l1w + (size_t)l * D * D, N);
        edge_kernel<<<ge, ETHREADS, EDGE_SMEM>>>(attr, eidx, elen,
                                            w1 + (size_t)l * D * G, b1 + (size_t)l * D,
                                            w2 + (size_t)l * D * D, b2 + (size_t)l * D, E);
        float* hout = (l == NLAYERS - 1) ? (float*)d_out : nullptr;
        update_kernel<<<gu, UTHREADS, UPD_SMEM>>>(l2w + (size_t)l * D * D, l2b + (size_t)l * D,
                                             lw + (size_t)l * D * 2 * D, lb + (size_t)l * D,
                                             N, hout);
    }
}

// round 10
// speedup vs baseline: 2.1052x; 1.1865x over previous
#include <cuda_runtime.h>
#include <cuda_fp16.h>
#include <cstdint>
#include <math.h>

#define D 128
#define G 100
#define NLAYERS 6
#define ZDIM 133
#define IND 5
#define NMAX 20000
#define EMAX 320000
#define LOG2F_ 0.6931471805599453f

extern __shared__ char dynsmem[];

// ---------------- scratch ----------------
__device__ __align__(256) float g_h [NMAX * D];
__device__ __align__(256) float g_xf[NMAX * D];
__device__ __align__(256) float g_mi[NMAX * D];

__device__ __forceinline__ float ssp_f(float x) {
    float sp = (x > 15.0f) ? x : log1pf(__expf(x));
    return sp - LOG2F_;
}

__device__ __forceinline__ uint32_t pack_half2(float lo, float hi) {
    __half2 h = __floats2half2_rn(lo, hi);
    return *reinterpret_cast<uint32_t*>(&h);
}

__device__ __forceinline__ uint32_t smem_u32(const void* p) {
    uint32_t a;
    asm("{ .reg .u64 t; cvta.to.shared.u64 t, %1; cvt.u32.u64 %0, t; }" : "=r"(a) : "l"(p));
    return a;
}

// D(16x8) += A(16x16) * B(16x8),  f16 operands, f32 accum
__device__ __forceinline__ void mma_f16(float* d, const uint32_t* a,
                                        const uint32_t* b, const float* c) {
    asm volatile(
        "mma.sync.aligned.m16n8k16.row.col.f32.f16.f16.f32 "
        "{%0,%1,%2,%3}, {%4,%5,%6,%7}, {%8,%9}, {%10,%11,%12,%13};"
        : "=f"(d[0]), "=f"(d[1]), "=f"(d[2]), "=f"(d[3])
        : "r"(a[0]), "r"(a[1]), "r"(a[2]), "r"(a[3]),
          "r"(b[0]), "r"(b[1]),
          "f"(c[0]), "f"(c[1]), "f"(c[2]), "f"(c[3]));
}

#define LDSM_X4(r, addr)                                                     \
    asm volatile("ldmatrix.sync.aligned.m8n8.x4.shared.b16 {%0,%1,%2,%3}, [%4];" \
        : "=r"((r)[0]), "=r"((r)[1]), "=r"((r)[2]), "=r"((r)[3]) : "r"(addr))

// ---------------- embed ----------------
__global__ void embed_kernel(const float* __restrict__ z,
                             const float* __restrict__ w,
                             const float* __restrict__ b, int N) {
    int gid = blockIdx.x * blockDim.x + threadIdx.x;
    if (gid >= N * D) return;
    int i = gid >> 7, d = gid & 127;
    const float* zr = z + (size_t)i * ZDIM;
    float acc = b[d] + zr[IND + d];
#pragma unroll
    for (int k = 0; k < IND; k++) acc += zr[k] * w[d * IND + k];
    g_h[gid] = acc;
}

// ---------------- xf = h @ lin1^T ; zero m_i ----------------
__global__ void xf_kernel(const float* __restrict__ lin1, int N) {
    float* smem = reinterpret_cast<float*>(dynsmem);
    float* wt = smem;
    float* hs = wt + D * D;
    int tid = threadIdx.x;
    for (int idx = tid; idx < D * D; idx += 256) {
        int d = idx >> 7, k = idx & 127;
        wt[k * D + d] = lin1[idx];
    }
    int tx = tid & 31, ty = tid >> 5;
    int ntiles = (N + 63) >> 6;
    for (int t = blockIdx.x; t < ntiles; t += gridDim.x) {
        int r0 = t << 6;
        __syncthreads();
        for (int idx = tid; idx < 64 * D; idx += 256) {
            int r = r0 + (idx >> 7);
            hs[idx] = (r < N) ? g_h[r * D + (idx & 127)] : 0.f;
        }
        for (int idx = tid; idx < 64 * 32; idx += 256) {
            int r = r0 + (idx >> 5);
            if (r < N)
                reinterpret_cast<float4*>(g_mi)[r * 32 + (idx & 31)] =
                    make_float4(0.f, 0.f, 0.f, 0.f);
        }
        __syncthreads();
        float4 acc[8];
#pragma unroll
        for (int j = 0; j < 8; j++) acc[j] = make_float4(0.f, 0.f, 0.f, 0.f);
#pragma unroll 4
        for (int k = 0; k < D; k++) {
            float4 w = *reinterpret_cast<const float4*>(&wt[k * D + tx * 4]);
#pragma unroll
            for (int j = 0; j < 8; j++) {
                float a = hs[(ty * 8 + j) * D + k];
                acc[j].x += a * w.x; acc[j].y += a * w.y;
                acc[j].z += a * w.z; acc[j].w += a * w.w;
            }
        }
#pragma unroll
        for (int j = 0; j < 8; j++) {
            int r = r0 + ty * 8 + j;
            if (r < N)
                *reinterpret_cast<float4*>(&g_xf[r * D + tx * 4]) = acc[j];
        }
    }
}

// ---------------- fp16 mma edge kernel ----------------
// byte offsets in dynamic smem:
//   AT0/AT1: half[128][120] attr double buffer (row stride 240B)
//   HBWF:    half[128][136] H (stride 272B)  ALIASED with  float[128][132] Wf
//   W1N:     half[128 n][120] (k-major-in-row, K pad 100->112)
//   W2N:     half[128 n][136] (K=128)
#define OFF_AT0  0
#define OFF_AT1  30720
#define OFF_HBWF 61440
#define OFF_W1N  129024
#define OFF_W2N  159744
#define OFF_B1E  194560
#define OFF_B2E  195072
#define OFF_SRCE 195584
#define OFF_DSTE 196608
#define OFF_CSE  197632
#define EDGE_SMEM 198656
#define ETHREADS 512

__device__ __forceinline__ void stage_tile(char* dyn, uint32_t bufoff, int slot,
                                           const float* __restrict__ attr,
                                           const int* __restrict__ eidx,
                                           const float* __restrict__ elen,
                                           int e0, int E, int tid) {
    for (int idx = tid; idx < 128 * 25; idx += ETHREADS) {
        int r = idx / 25, ck = idx - r * 25;
        int e = e0 + r;
        float4 v = make_float4(0.f, 0.f, 0.f, 0.f);
        if (e < E)
            v = *reinterpret_cast<const float4*>(attr + (size_t)e * G + ck * 4);
        uint2 u;
        u.x = pack_half2(v.x, v.y);
        u.y = pack_half2(v.z, v.w);
        *reinterpret_cast<uint2*>(dyn + bufoff + r * 240 + ck * 8) = u;
    }
    if (tid < 128) {
        uint2 z = make_uint2(0u, 0u);
        char* p = dyn + bufoff + tid * 240 + 200;
        reinterpret_cast<uint2*>(p)[0] = z;
        reinterpret_cast<uint2*>(p)[1] = z;
        reinterpret_cast<uint2*>(p)[2] = z;
        int e = e0 + tid;
        int s = 0, d = 0; float c = 0.f;
        if (e < E) {
            s = eidx[e]; d = eidx[E + e];
            c = (elen[e] <= 10.0f) ? 1.0f : 0.0f;
        }
        reinterpret_cast<int*>(dyn + OFF_SRCE + slot * 512)[tid] = s;
        reinterpret_cast<int*>(dyn + OFF_DSTE + slot * 512)[tid] = d;
        reinterpret_cast<float*>(dyn + OFF_CSE + slot * 512)[tid] = c;
    }
}

__global__ __launch_bounds__(ETHREADS, 1)
void edge_kernel(const float* __restrict__ attr,
                 const int* __restrict__ eidx,
                 const float* __restrict__ elen,
                 const float* __restrict__ w1,
                 const float* __restrict__ b1,
                 const float* __restrict__ w2,
                 const float* __restrict__ b2, int E) {
    char* dyn = dynsmem;
    uint32_t sb = smem_u32(dyn);
    int tid = threadIdx.x, lane = tid & 31, wid = tid >> 5;
    int qr = lane >> 2, qc = lane & 3;
    int wm = (wid & 3) * 32;       // row base, 4 row groups of 32
    int wn = (wid >> 2) * 32;      // col base, 4 col groups of 32

    // --- stage weights as fp16, n-major ---
    for (int idx = tid; idx < 128 * 25; idx += ETHREADS) {
        int n = idx / 25, ck = idx - n * 25;
        float4 v = *reinterpret_cast<const float4*>(w1 + (size_t)n * G + ck * 4);
        uint2 u; u.x = pack_half2(v.x, v.y); u.y = pack_half2(v.z, v.w);
        *reinterpret_cast<uint2*>(dyn + OFF_W1N + n * 240 + ck * 8) = u;
    }
    if (tid < 128) {
        uint2 z = make_uint2(0u, 0u);
        char* p = dyn + OFF_W1N + tid * 240 + 200;
        reinterpret_cast<uint2*>(p)[0] = z;
        reinterpret_cast<uint2*>(p)[1] = z;
        reinterpret_cast<uint2*>(p)[2] = z;
    }
    for (int idx = tid; idx < 128 * 32; idx += ETHREADS) {
        int n = idx >> 5, ck = idx & 31;
        float4 v = *reinterpret_cast<const float4*>(w2 + (size_t)n * D + ck * 4);
        uint2 u; u.x = pack_half2(v.x, v.y); u.y = pack_half2(v.z, v.w);
        *reinterpret_cast<uint2*>(dyn + OFF_W2N + n * 272 + ck * 8) = u;
    }
    if (tid < 128) {
        reinterpret_cast<float*>(dyn + OFF_B1E)[tid] = b1[tid];
        reinterpret_cast<float*>(dyn + OFF_B2E)[tid] = b2[tid];
    }
    const float* b1s = reinterpret_cast<const float*>(dyn + OFF_B1E);
    const float* b2s = reinterpret_cast<const float*>(dyn + OFF_B2E);

    int ntiles = (E + 127) >> 7;
    uint32_t atoff[2] = {OFF_AT0, OFF_AT1};

    // prologue: stage first tile into buffer 0
    if ((int)blockIdx.x < ntiles)
        stage_tile(dyn, atoff[0], 0, attr, eidx, elen, (int)blockIdx.x << 7, E, tid);
    __syncthreads();

    int b = 0;
    for (int t = blockIdx.x; t < ntiles; t += gridDim.x, b ^= 1) {
        int e0 = t << 7;
        const int* srcs = reinterpret_cast<const int*>(dyn + OFF_SRCE + b * 512);
        const int* dsts = reinterpret_cast<const int*>(dyn + OFF_DSTE + b * 512);
        const float* cs = reinterpret_cast<const float*>(dyn + OFF_CSE + b * 512);

        float acc[2][4][4];
#pragma unroll
        for (int mt = 0; mt < 2; mt++)
#pragma unroll
            for (int nt = 0; nt < 4; nt++)
#pragma unroll
                for (int i = 0; i < 4; i++) acc[mt][nt][i] = 0.f;

        // GEMM1: C1 = attr @ W1^T  (K=112)
#pragma unroll
        for (int ks = 0; ks < 7; ks++) {
            int k0h = ks * 16;
            uint32_t af[2][4], bf[2][4];
#pragma unroll
            for (int mt = 0; mt < 2; mt++) {
                uint32_t addr = sb + atoff[b] +
                    (wm + mt * 16 + (lane & 15)) * 240 +
                    (k0h + ((lane >> 4) << 3)) * 2;
                LDSM_X4(af[mt], addr);
            }
#pragma unroll
            for (int p = 0; p < 2; p++) {
                uint32_t addr = sb + OFF_W1N +
                    (wn + p * 16 + ((lane >> 4) << 3) + (lane & 7)) * 240 +
                    (k0h + (((lane >> 3) & 1) << 3)) * 2;
                LDSM_X4(bf[p], addr);
            }
#pragma unroll
            for (int mt = 0; mt < 2; mt++)
#pragma unroll
                for (int nt = 0; nt < 4; nt++)
                    mma_f16(acc[mt][nt], af[mt], &bf[nt >> 1][(nt & 1) * 2], acc[mt][nt]);
        }

        // H = fp16(ssp(C1 + b1)) -> HBWF  (clobbers prev Wf: safe, prev epilogue done)
#pragma unroll
        for (int mt = 0; mt < 2; mt++) {
            int row = wm + mt * 16 + qr;
#pragma unroll
            for (int nt = 0; nt < 4; nt++) {
                int col = wn + nt * 8 + qc * 2;
                float bb0 = b1s[col], bb1 = b1s[col + 1];
                uint32_t lo = pack_half2(ssp_f(acc[mt][nt][0] + bb0),
                                         ssp_f(acc[mt][nt][1] + bb1));
                uint32_t hi = pack_half2(ssp_f(acc[mt][nt][2] + bb0),
                                         ssp_f(acc[mt][nt][3] + bb1));
                *reinterpret_cast<uint32_t*>(dyn + OFF_HBWF + row * 272 + col * 2) = lo;
                *reinterpret_cast<uint32_t*>(dyn + OFF_HBWF + (row + 8) * 272 + col * 2) = hi;
            }
        }
        __syncthreads();

        // prefetch xf gather (current tile) — latency hides under GEMM2
        float4 xf_pref[8];
        {
            int prow = tid >> 2, pq = tid & 3;
            if (e0 + prow < E) {
                const float4* pxp = reinterpret_cast<const float4*>(
                    g_xf + (size_t)srcs[prow] * D + pq * 32);
#pragma unroll
                for (int i = 0; i < 8; i++) xf_pref[i] = pxp[i];
            } else {
#pragma unroll
                for (int i = 0; i < 8; i++) xf_pref[i] = make_float4(0.f, 0.f, 0.f, 0.f);
            }
        }
        // stage NEXT tile into the other buffer
        if (t + (int)gridDim.x < ntiles)
            stage_tile(dyn, atoff[b ^ 1], b ^ 1, attr, eidx, elen,
                       (t + (int)gridDim.x) << 7, E, tid);

#pragma unroll
        for (int mt = 0; mt < 2; mt++)
#pragma unroll
            for (int nt = 0; nt < 4; nt++)
#pragma unroll
                for (int i = 0; i < 4; i++) acc[mt][nt][i] = 0.f;

        // GEMM2: C2 = H @ W2^T  (K=128)
#pragma unroll
        for (int ks = 0; ks < 8; ks++) {
            int k0h = ks * 16;
            uint32_t af[2][4], bf[2][4];
#pragma unroll
            for (int mt = 0; mt < 2; mt++) {
                uint32_t addr = sb + OFF_HBWF +
                    (wm + mt * 16 + (lane & 15)) * 272 +
                    (k0h + ((lane >> 4) << 3)) * 2;
                LDSM_X4(af[mt], addr);
            }
#pragma unroll
            for (int p = 0; p < 2; p++) {
                uint32_t addr = sb + OFF_W2N +
                    (wn + p * 16 + ((lane >> 4) << 3) + (lane & 7)) * 272 +
                    (k0h + (((lane >> 3) & 1) << 3)) * 2;
                LDSM_X4(bf[p], addr);
            }
#pragma unroll
            for (int mt = 0; mt < 2; mt++)
#pragma unroll
                for (int nt = 0; nt < 4; nt++)
                    mma_f16(acc[mt][nt], af[mt], &bf[nt >> 1][(nt & 1) * 2], acc[mt][nt]);
        }
        __syncthreads();   // all H reads done (and next-tile staging complete)

        // Wf = (C2 + b2) * C -> float over HBWF
        {
            float* wf = reinterpret_cast<float*>(dyn + OFF_HBWF);
#pragma unroll
            for (int mt = 0; mt < 2; mt++) {
                int row = wm + mt * 16 + qr;
                float c0 = cs[row], c1 = cs[row + 8];
#pragma unroll
                for (int nt = 0; nt < 4; nt++) {
                    int col = wn + nt * 8 + qc * 2;
                    float bb0 = b2s[col], bb1 = b2s[col + 1];
                    float2 lo, hi;
                    lo.x = (acc[mt][nt][0] + bb0) * c0;
                    lo.y = (acc[mt][nt][1] + bb1) * c0;
                    hi.x = (acc[mt][nt][2] + bb0) * c1;
                    hi.y = (acc[mt][nt][3] + bb1) * c1;
                    *reinterpret_cast<float2*>(wf + row * 132 + col) = lo;
                    *reinterpret_cast<float2*>(wf + (row + 8) * 132 + col) = hi;
                }
            }
        }
        __syncthreads();

        // epilogue: m_ij = xf_pref * Wf; red-add into m_i[dst]
        {
            const float* wfb = reinterpret_cast<const float*>(dyn + OFF_HBWF);
            int row = tid >> 2, q = tid & 3;
            if (e0 + row < E) {
                float* mp = g_mi + (size_t)dsts[row] * D + q * 32;
                const float* wf = wfb + row * 132 + q * 32;
#pragma unroll
                for (int i = 0; i < 8; i++) {
                    float4 w = *reinterpret_cast<const float4*>(wf + i * 4);
                    float4 x = xf_pref[i];
                    float rx = w.x * x.x, ry = w.y * x.y;
                    float rz = w.z * x.z, rw = w.w * x.w;
                    asm volatile("red.global.add.v4.f32 [%0], {%1,%2,%3,%4};"
                                 :: "l"(mp + i * 4), "f"(rx), "f"(ry),
                                    "f"(rz), "f"(rw) : "memory");
                }
            }
        }
        __syncthreads();   // epilogue done before next iter's H store
    }
}

// ---------------- fused update (512 threads) ----------------
#define UTHREADS 512
__global__ __launch_bounds__(UTHREADS, 1)
void update_kernel(const float* __restrict__ lin2w,
                   const float* __restrict__ lin2b,
                   const float* __restrict__ linw,
                   const float* __restrict__ linb,
                   int N, float* __restrict__ hout) {
    float* smem = reinterpret_cast<float*>(dynsmem);
    float* l2t = smem;
    float* lat = l2t + D * D;
    float* lbt = lat + D * D;
    float* b2s = lbt + D * D;
    float* bls = b2s + D;
    float* hsm = bls + D;
    float* msm = hsm + 32 * D;
    int tid = threadIdx.x;

    for (int idx = tid; idx < D * D; idx += UTHREADS) {
        int d = idx >> 7, k = idx & 127;
        l2t[k * D + d] = lin2w[idx];
    }
    for (int idx = tid; idx < D * 2 * D; idx += UTHREADS) {
        int d = idx >> 8, c = idx & 255;
        float v = linw[idx];
        if (c < D) lat[c * D + d] = v;
        else       lbt[(c - D) * D + d] = v;
    }
    if (tid < D) { b2s[tid] = lin2b[tid]; bls[tid] = linb[tid]; }

    int tx = tid & 31, ty = tid >> 5;
    int ntiles = (N + 31) >> 5;
    for (int t = blockIdx.x; t < ntiles; t += gridDim.x) {
        int r0 = t << 5;
        __syncthreads();
        for (int idx = tid; idx < 32 * D; idx += UTHREADS) {
            int r = r0 + (idx >> 7);
            hsm[idx] = (r < N) ? g_h[r * D + (idx & 127)] : 0.f;
            msm[idx] = (r < N) ? g_mi[r * D + (idx & 127)] : 0.f;
        }
        __syncthreads();

        float4 a[2];
#pragma unroll
        for (int j = 0; j < 2; j++) a[j] = make_float4(0.f, 0.f, 0.f, 0.f);
#pragma unroll 4
        for (int k = 0; k < D; k++) {
            float4 w = *reinterpret_cast<const float4*>(&l2t[k * D + tx * 4]);
#pragma unroll
            for (int j = 0; j < 2; j++) {
                float v = msm[(ty * 2 + j) * D + k];
                a[j].x += v * w.x; a[j].y += v * w.y;
                a[j].z += v * w.z; a[j].w += v * w.w;
            }
        }
        float4 b2v = *reinterpret_cast<const float4*>(&b2s[tx * 4]);
        float4 mval[2];
#pragma unroll
        for (int j = 0; j < 2; j++) {
            mval[j].x = ssp_f(a[j].x + b2v.x);
            mval[j].y = ssp_f(a[j].y + b2v.y);
            mval[j].z = ssp_f(a[j].z + b2v.z);
            mval[j].w = ssp_f(a[j].w + b2v.w);
        }
        __syncthreads();
#pragma unroll
        for (int j = 0; j < 2; j++)
            *reinterpret_cast<float4*>(&msm[(ty * 2 + j) * D + tx * 4]) = mval[j];
        __syncthreads();

        float4 o[2];
        float4 blv = *reinterpret_cast<const float4*>(&bls[tx * 4]);
#pragma unroll
        for (int j = 0; j < 2; j++) {
            float4 h0 = *reinterpret_cast<const float4*>(
                &hsm[(ty * 2 + j) * D + tx * 4]);
            o[j].x = h0.x + blv.x; o[j].y = h0.y + blv.y;
            o[j].z = h0.z + blv.z; o[j].w = h0.w + blv.w;
        }
#pragma unroll 4
        for (int k = 0; k < D; k++) {
            float4 wa = *reinterpret_cast<const float4*>(&lat[k * D + tx * 4]);
            float4 wb = *reinterpret_cast<const float4*>(&lbt[k * D + tx * 4]);
#pragma unroll
            for (int j = 0; j < 2; j++) {
                float hv = hsm[(ty * 2 + j) * D + k];
                float mv = msm[(ty * 2 + j) * D + k];
                o[j].x += hv * wa.x + mv * wb.x;
                o[j].y += hv * wa.y + mv * wb.y;
                o[j].z += hv * wa.z + mv * wb.z;
                o[j].w += hv * wa.w + mv * wb.w;
            }
        }
        float* outp = hout ? hout : g_h;
#pragma unroll
        for (int j = 0; j < 2; j++) {
            int r = r0 + ty * 2 + j;
            if (r < N)
                *reinterpret_cast<float4*>(&outp[r * D + tx * 4]) = o[j];
        }
    }
}

// ---------------- launch ----------------
extern "C" void kernel_launch(void* const* d_in, const int* in_sizes, int n_in,
                              void* d_out, int out_size) {
    const float* z    = (const float*)d_in[0];
    const int*   eidx = (const int*)d_in[1];
    const float* elen = (const float*)d_in[2];
    const float* attr = (const float*)d_in[3];
    const float* embw = (const float*)d_in[4];
    const float* embb = (const float*)d_in[5];
    const float* w1   = (const float*)d_in[6];
    const float* b1   = (const float*)d_in[7];
    const float* w2   = (const float*)d_in[8];
    const float* b2   = (const float*)d_in[9];
    const float* l1w  = (const float*)d_in[10];
    const float* l2w  = (const float*)d_in[11];
    const float* l2b  = (const float*)d_in[12];
    const float* lw   = (const float*)d_in[13];
    const float* lb   = (const float*)d_in[14];

    int N = in_sizes[0] / ZDIM;
    int E = in_sizes[2];

    const int XF_SMEM  = (D * D + 64 * D) * 4;
    const int UPD_SMEM = (3 * D * D + 2 * D + 64 * D) * 4;

    cudaFuncSetAttribute(xf_kernel,     cudaFuncAttributeMaxDynamicSharedMemorySize, XF_SMEM);
    cudaFuncSetAttribute(edge_kernel,   cudaFuncAttributeMaxDynamicSharedMemorySize, EDGE_SMEM);
    cudaFuncSetAttribute(update_kernel, cudaFuncAttributeMaxDynamicSharedMemorySize, UPD_SMEM);

    int nsm = 148;
    cudaDeviceGetAttribute(&nsm, cudaDevAttrMultiProcessorCount, 0);

    int etiles = (E + 127) >> 7;
    int xtiles = (N + 63) >> 6;
    int utiles = (N + 31) >> 5;
    int gx = 2 * nsm < xtiles ? 2 * nsm : xtiles;
    int ge = nsm < etiles ? nsm : etiles;
    int gu = nsm < utiles ? nsm : utiles;

    embed_kernel<<<(N * D + 255) / 256, 256>>>(z, embw, embb, N);

    for (int l = 0; l < NLAYERS; l++) {
        xf_kernel<<<gx, 256, XF_SMEM>>>(l1w + (size_t)l * D * D, N);
        edge_kernel<<<ge, ETHREADS, EDGE_SMEM>>>(attr, eidx, elen,
                                            w1 + (size_t)l * D * G, b1 + (size_t)l * D,
                                            w2 + (size_t)l * D * D, b2 + (size_t)l * D, E);
        float* hout = (l == NLAYERS - 1) ? (float*)d_out : nullptr;
        update_kernel<<<gu, UTHREADS, UPD_SMEM>>>(l2w + (size_t)l * D * D, l2b + (size_t)l * D,
                                             lw + (size_t)l * D * 2 * D, lb + (size_t)l * D,
                                             N, hout);
    }
}

// round 12
// speedup vs baseline: 2.7373x; 1.3003x over previous
#include <cuda_runtime.h>
#include <cuda_fp16.h>
#include <cstdint>
#include <math.h>

#define D 128
#define G 100
#define NLAYERS 6
#define ZDIM 133
#define IND 5
#define NMAX 20000
#define EMAX 320000
#define LOG2F_ 0.6931471805599453f

extern __shared__ char dynsmem[];

// ---------------- scratch ----------------
__device__ __align__(256) float g_h [NMAX * D];
__device__ __align__(256) float g_xf[NMAX * D];
__device__ __align__(256) float g_mi[NMAX * D];

__device__ __forceinline__ float ssp_f(float x) {
    float sp = (x > 15.0f) ? x : log1pf(__expf(x));
    return sp - LOG2F_;
}

__device__ __forceinline__ uint32_t pack_half2(float lo, float hi) {
    __half2 h = __floats2half2_rn(lo, hi);
    return *reinterpret_cast<uint32_t*>(&h);
}

__device__ __forceinline__ uint32_t smem_u32(const void* p) {
    uint32_t a;
    asm("{ .reg .u64 t; cvta.to.shared.u64 t, %1; cvt.u32.u64 %0, t; }" : "=r"(a) : "l"(p));
    return a;
}

// D(16x8) += A(16x16) * B(16x8),  f16 operands, f32 accum
__device__ __forceinline__ void mma_f16(float* d, const uint32_t* a,
                                        const uint32_t* b, const float* c) {
    asm volatile(
        "mma.sync.aligned.m16n8k16.row.col.f32.f16.f16.f32 "
        "{%0,%1,%2,%3}, {%4,%5,%6,%7}, {%8,%9}, {%10,%11,%12,%13};"
        : "=f"(d[0]), "=f"(d[1]), "=f"(d[2]), "=f"(d[3])
        : "r"(a[0]), "r"(a[1]), "r"(a[2]), "r"(a[3]),
          "r"(b[0]), "r"(b[1]),
          "f"(c[0]), "f"(c[1]), "f"(c[2]), "f"(c[3]));
}

#define LDSM_X4(r, addr)                                                     \
    asm volatile("ldmatrix.sync.aligned.m8n8.x4.shared.b16 {%0,%1,%2,%3}, [%4];" \
        : "=r"((r)[0]), "=r"((r)[1]), "=r"((r)[2]), "=r"((r)[3]) : "r"(addr))

// ---------------- embed ----------------
__global__ void embed_kernel(const float* __restrict__ z,
                             const float* __restrict__ w,
                             const float* __restrict__ b, int N) {
    int gid = blockIdx.x * blockDim.x + threadIdx.x;
    if (gid >= N * D) return;
    int i = gid >> 7, d = gid & 127;
    const float* zr = z + (size_t)i * ZDIM;
    float acc = b[d] + zr[IND + d];
#pragma unroll
    for (int k = 0; k < IND; k++) acc += zr[k] * w[d * IND + k];
    g_h[gid] = acc;
}

// ---------------- xf0 = h @ lin1[0]^T ; zero m_i  (layer 0 only) ----------------
__global__ void xf_kernel(const float* __restrict__ lin1, int N) {
    float* smem = reinterpret_cast<float*>(dynsmem);
    float* wt = smem;
    float* hs = wt + D * D;
    int tid = threadIdx.x;
    for (int idx = tid; idx < D * D; idx += 256) {
        int d = idx >> 7, k = idx & 127;
        wt[k * D + d] = lin1[idx];
    }
    int tx = tid & 31, ty = tid >> 5;
    int ntiles = (N + 63) >> 6;
    for (int t = blockIdx.x; t < ntiles; t += gridDim.x) {
        int r0 = t << 6;
        __syncthreads();
        for (int idx = tid; idx < 64 * D; idx += 256) {
            int r = r0 + (idx >> 7);
            hs[idx] = (r < N) ? g_h[r * D + (idx & 127)] : 0.f;
        }
        for (int idx = tid; idx < 64 * 32; idx += 256) {
            int r = r0 + (idx >> 5);
            if (r < N)
                reinterpret_cast<float4*>(g_mi)[r * 32 + (idx & 31)] =
                    make_float4(0.f, 0.f, 0.f, 0.f);
        }
        __syncthreads();
        float4 acc[8];
#pragma unroll
        for (int j = 0; j < 8; j++) acc[j] = make_float4(0.f, 0.f, 0.f, 0.f);
#pragma unroll 4
        for (int k = 0; k < D; k++) {
            float4 w = *reinterpret_cast<const float4*>(&wt[k * D + tx * 4]);
#pragma unroll
            for (int j = 0; j < 8; j++) {
                float a = hs[(ty * 8 + j) * D + k];
                acc[j].x += a * w.x; acc[j].y += a * w.y;
                acc[j].z += a * w.z; acc[j].w += a * w.w;
            }
        }
#pragma unroll
        for (int j = 0; j < 8; j++) {
            int r = r0 + ty * 8 + j;
            if (r < N)
                *reinterpret_cast<float4*>(&g_xf[r * D + tx * 4]) = acc[j];
        }
    }
}

// ---------------- fp16 mma edge kernel (unchanged from R10) ----------------
#define OFF_AT0  0
#define OFF_AT1  30720
#define OFF_HBWF 61440
#define OFF_W1N  129024
#define OFF_W2N  159744
#define OFF_B1E  194560
#define OFF_B2E  195072
#define OFF_SRCE 195584
#define OFF_DSTE 196608
#define OFF_CSE  197632
#define EDGE_SMEM 198656
#define ETHREADS 512

__device__ __forceinline__ void stage_tile(char* dyn, uint32_t bufoff, int slot,
                                           const float* __restrict__ attr,
                                           const int* __restrict__ eidx,
                                           const float* __restrict__ elen,
                                           int e0, int E, int tid) {
    for (int idx = tid; idx < 128 * 25; idx += ETHREADS) {
        int r = idx / 25, ck = idx - r * 25;
        int e = e0 + r;
        float4 v = make_float4(0.f, 0.f, 0.f, 0.f);
        if (e < E)
            v = *reinterpret_cast<const float4*>(attr + (size_t)e * G + ck * 4);
        uint2 u;
        u.x = pack_half2(v.x, v.y);
        u.y = pack_half2(v.z, v.w);
        *reinterpret_cast<uint2*>(dyn + bufoff + r * 240 + ck * 8) = u;
    }
    if (tid < 128) {
        uint2 z = make_uint2(0u, 0u);
        char* p = dyn + bufoff + tid * 240 + 200;
        reinterpret_cast<uint2*>(p)[0] = z;
        reinterpret_cast<uint2*>(p)[1] = z;
        reinterpret_cast<uint2*>(p)[2] = z;
        int e = e0 + tid;
        int s = 0, d = 0; float c = 0.f;
        if (e < E) {
            s = eidx[e]; d = eidx[E + e];
            c = (elen[e] <= 10.0f) ? 1.0f : 0.0f;
        }
        reinterpret_cast<int*>(dyn + OFF_SRCE + slot * 512)[tid] = s;
        reinterpret_cast<int*>(dyn + OFF_DSTE + slot * 512)[tid] = d;
        reinterpret_cast<float*>(dyn + OFF_CSE + slot * 512)[tid] = c;
    }
}

__global__ __launch_bounds__(ETHREADS, 1)
void edge_kernel(const float* __restrict__ attr,
                 const int* __restrict__ eidx,
                 const float* __restrict__ elen,
                 const float* __restrict__ w1,
                 const float* __restrict__ b1,
                 const float* __restrict__ w2,
                 const float* __restrict__ b2, int E) {
    char* dyn = dynsmem;
    uint32_t sb = smem_u32(dyn);
    int tid = threadIdx.x, lane = tid & 31, wid = tid >> 5;
    int qr = lane >> 2, qc = lane & 3;
    int wm = (wid & 3) * 32;
    int wn = (wid >> 2) * 32;

    for (int idx = tid; idx < 128 * 25; idx += ETHREADS) {
        int n = idx / 25, ck = idx - n * 25;
        float4 v = *reinterpret_cast<const float4*>(w1 + (size_t)n * G + ck * 4);
        uint2 u; u.x = pack_half2(v.x, v.y); u.y = pack_half2(v.z, v.w);
        *reinterpret_cast<uint2*>(dyn + OFF_W1N + n * 240 + ck * 8) = u;
    }
    if (tid < 128) {
        uint2 z = make_uint2(0u, 0u);
        char* p = dyn + OFF_W1N + tid * 240 + 200;
        reinterpret_cast<uint2*>(p)[0] = z;
        reinterpret_cast<uint2*>(p)[1] = z;
        reinterpret_cast<uint2*>(p)[2] = z;
    }
    for (int idx = tid; idx < 128 * 32; idx += ETHREADS) {
        int n = idx >> 5, ck = idx & 31;
        float4 v = *reinterpret_cast<const float4*>(w2 + (size_t)n * D + ck * 4);
        uint2 u; u.x = pack_half2(v.x, v.y); u.y = pack_half2(v.z, v.w);
        *reinterpret_cast<uint2*>(dyn + OFF_W2N + n * 272 + ck * 8) = u;
    }
    if (tid < 128) {
        reinterpret_cast<float*>(dyn + OFF_B1E)[tid] = b1[tid];
        reinterpret_cast<float*>(dyn + OFF_B2E)[tid] = b2[tid];
    }
    const float* b1s = reinterpret_cast<const float*>(dyn + OFF_B1E);
    const float* b2s = reinterpret_cast<const float*>(dyn + OFF_B2E);

    int ntiles = (E + 127) >> 7;
    uint32_t atoff[2] = {OFF_AT0, OFF_AT1};

    if ((int)blockIdx.x < ntiles)
        stage_tile(dyn, atoff[0], 0, attr, eidx, elen, (int)blockIdx.x << 7, E, tid);
    __syncthreads();

    int b = 0;
    for (int t = blockIdx.x; t < ntiles; t += gridDim.x, b ^= 1) {
        int e0 = t << 7;
        const int* srcs = reinterpret_cast<const int*>(dyn + OFF_SRCE + b * 512);
        const int* dsts = reinterpret_cast<const int*>(dyn + OFF_DSTE + b * 512);
        const float* cs = reinterpret_cast<const float*>(dyn + OFF_CSE + b * 512);

        float acc[2][4][4];
#pragma unroll
        for (int mt = 0; mt < 2; mt++)
#pragma unroll
            for (int nt = 0; nt < 4; nt++)
#pragma unroll
                for (int i = 0; i < 4; i++) acc[mt][nt][i] = 0.f;

#pragma unroll
        for (int ks = 0; ks < 7; ks++) {
            int k0h = ks * 16;
            uint32_t af[2][4], bf[2][4];
#pragma unroll
            for (int mt = 0; mt < 2; mt++) {
                uint32_t addr = sb + atoff[b] +
                    (wm + mt * 16 + (lane & 15)) * 240 +
                    (k0h + ((lane >> 4) << 3)) * 2;
                LDSM_X4(af[mt], addr);
            }
#pragma unroll
            for (int p = 0; p < 2; p++) {
                uint32_t addr = sb + OFF_W1N +
                    (wn + p * 16 + ((lane >> 4) << 3) + (lane & 7)) * 240 +
                    (k0h + (((lane >> 3) & 1) << 3)) * 2;
                LDSM_X4(bf[p], addr);
            }
#pragma unroll
            for (int mt = 0; mt < 2; mt++)
#pragma unroll
                for (int nt = 0; nt < 4; nt++)
                    mma_f16(acc[mt][nt], af[mt], &bf[nt >> 1][(nt & 1) * 2], acc[mt][nt]);
        }

#pragma unroll
        for (int mt = 0; mt < 2; mt++) {
            int row = wm + mt * 16 + qr;
#pragma unroll
            for (int nt = 0; nt < 4; nt++) {
                int col = wn + nt * 8 + qc * 2;
                float bb0 = b1s[col], bb1 = b1s[col + 1];
                uint32_t lo = pack_half2(ssp_f(acc[mt][nt][0] + bb0),
                                         ssp_f(acc[mt][nt][1] + bb1));
                uint32_t hi = pack_half2(ssp_f(acc[mt][nt][2] + bb0),
                                         ssp_f(acc[mt][nt][3] + bb1));
                *reinterpret_cast<uint32_t*>(dyn + OFF_HBWF + row * 272 + col * 2) = lo;
                *reinterpret_cast<uint32_t*>(dyn + OFF_HBWF + (row + 8) * 272 + col * 2) = hi;
            }
        }
        __syncthreads();

        float4 xf_pref[8];
        {
            int prow = tid >> 2, pq = tid & 3;
            if (e0 + prow < E) {
                const float4* pxp = reinterpret_cast<const float4*>(
                    g_xf + (size_t)srcs[prow] * D + pq * 32);
#pragma unroll
                for (int i = 0; i < 8; i++) xf_pref[i] = pxp[i];
            } else {
#pragma unroll
                for (int i = 0; i < 8; i++) xf_pref[i] = make_float4(0.f, 0.f, 0.f, 0.f);
            }
        }
        if (t + (int)gridDim.x < ntiles)
            stage_tile(dyn, atoff[b ^ 1], b ^ 1, attr, eidx, elen,
                       (t + (int)gridDim.x) << 7, E, tid);

#pragma unroll
        for (int mt = 0; mt < 2; mt++)
#pragma unroll
            for (int nt = 0; nt < 4; nt++)
#pragma unroll
                for (int i = 0; i < 4; i++) acc[mt][nt][i] = 0.f;

#pragma unroll
        for (int ks = 0; ks < 8; ks++) {
            int k0h = ks * 16;
            uint32_t af[2][4], bf[2][4];
#pragma unroll
            for (int mt = 0; mt < 2; mt++) {
                uint32_t addr = sb + OFF_HBWF +
                    (wm + mt * 16 + (lane & 15)) * 272 +
                    (k0h + ((lane >> 4) << 3)) * 2;
                LDSM_X4(af[mt], addr);
            }
#pragma unroll
            for (int p = 0; p < 2; p++) {
                uint32_t addr = sb + OFF_W2N +
                    (wn + p * 16 + ((lane >> 4) << 3) + (lane & 7)) * 272 +
                    (k0h + (((lane >> 3) & 1) << 3)) * 2;
                LDSM_X4(bf[p], addr);
            }
#pragma unroll
            for (int mt = 0; mt < 2; mt++)
#pragma unroll
                for (int nt = 0; nt < 4; nt++)
                    mma_f16(acc[mt][nt], af[mt], &bf[nt >> 1][(nt & 1) * 2], acc[mt][nt]);
        }
        __syncthreads();

        {
            float* wf = reinterpret_cast<float*>(dyn + OFF_HBWF);
#pragma unroll
            for (int mt = 0; mt < 2; mt++) {
                int row = wm + mt * 16 + qr;
                float c0 = cs[row], c1 = cs[row + 8];
#pragma unroll
                for (int nt = 0; nt < 4; nt++) {
                    int col = wn + nt * 8 + qc * 2;
                    float bb0 = b2s[col], bb1 = b2s[col + 1];
                    float2 lo, hi;
                    lo.x = (acc[mt][nt][0] + bb0) * c0;
                    lo.y = (acc[mt][nt][1] + bb1) * c0;
                    hi.x = (acc[mt][nt][2] + bb0) * c1;
                    hi.y = (acc[mt][nt][3] + bb1) * c1;
                    *reinterpret_cast<float2*>(wf + row * 132 + col) = lo;
                    *reinterpret_cast<float2*>(wf + (row + 8) * 132 + col) = hi;
                }
            }
        }
        __syncthreads();

        {
            const float* wfb = reinterpret_cast<const float*>(dyn + OFF_HBWF);
            int row = tid >> 2, q = tid & 3;
            if (e0 + row < E) {
                float* mp = g_mi + (size_t)dsts[row] * D + q * 32;
                const float* wf = wfb + row * 132 + q * 32;
#pragma unroll
                for (int i = 0; i < 8; i++) {
                    float4 w = *reinterpret_cast<const float4*>(wf + i * 4);
                    float4 x = xf_pref[i];
                    float rx = w.x * x.x, ry = w.y * x.y;
                    float rz = w.z * x.z, rw = w.w * x.w;
                    asm volatile("red.global.add.v4.f32 [%0], {%1,%2,%3,%4};"
                                 :: "l"(mp + i * 4), "f"(rx), "f"(ry),
                                    "f"(rz), "f"(rw) : "memory");
                }
            }
        }
        __syncthreads();
    }
}

// ---------------- fused node kernel: update + next-layer xf, fp16 mma ----------------
#define NO_L2N  0        // lin2   [n][k] f16, stride 272
#define NO_LAN  34816    // lin_w cols 0:128
#define NO_LBN  69632    // lin_w cols 128:256
#define NO_L1N  104448   // lin1 (next layer)
#define NO_HF32 139264   // float[64][132]
#define NO_H16  173056   // half, 64 rows stride 272
#define NO_M16  190464   // half, 64 rows stride 272
#define NO_B2   207872
#define NO_BL   208384
#define NODE_SMEM 208896
#define NTHREADS 512

__global__ __launch_bounds__(NTHREADS, 1)
void node_kernel(const float* __restrict__ lin2w,
                 const float* __restrict__ lin2b,
                 const float* __restrict__ linw,
                 const float* __restrict__ linb,
                 const float* __restrict__ lin1n,
                 int N, float* __restrict__ dout, int to_dout, int do_xf) {
    char* dyn = dynsmem;
    uint32_t sb = smem_u32(dyn);
    int tid = threadIdx.x, lane = tid & 31, wid = tid >> 5;
    int qr = lane >> 2, qc = lane & 3;
    int wm = (wid & 3) * 16;   // 4 row groups x 16 rows
    int wn = (wid >> 2) * 32;  // 4 col groups x 32 cols

    // device-side resolution of the intermediate output pointer (g_h is a
    // __device__ symbol — must NOT be taken from host code)
    float* outp = to_dout ? dout : g_h;

    // stage weights fp16, n-major
    for (int idx = tid; idx < 128 * 32; idx += NTHREADS) {
        int n = idx >> 5, ck = idx & 31;
        float4 v = *reinterpret_cast<const float4*>(lin2w + n * D + ck * 4);
        uint2 u; u.x = pack_half2(v.x, v.y); u.y = pack_half2(v.z, v.w);
        *reinterpret_cast<uint2*>(dyn + NO_L2N + n * 272 + ck * 8) = u;
    }
    for (int idx = tid; idx < 128 * 64; idx += NTHREADS) {
        int d_ = idx >> 6, c4 = idx & 63;
        float4 v = *reinterpret_cast<const float4*>(linw + d_ * 2 * D + c4 * 4);
        uint2 u; u.x = pack_half2(v.x, v.y); u.y = pack_half2(v.z, v.w);
        if (c4 < 32)
            *reinterpret_cast<uint2*>(dyn + NO_LAN + d_ * 272 + c4 * 8) = u;
        else
            *reinterpret_cast<uint2*>(dyn + NO_LBN + d_ * 272 + (c4 - 32) * 8) = u;
    }
    if (do_xf) {
        for (int idx = tid; idx < 128 * 32; idx += NTHREADS) {
            int n = idx >> 5, ck = idx & 31;
            float4 v = *reinterpret_cast<const float4*>(lin1n + n * D + ck * 4);
            uint2 u; u.x = pack_half2(v.x, v.y); u.y = pack_half2(v.z, v.w);
            *reinterpret_cast<uint2*>(dyn + NO_L1N + n * 272 + ck * 8) = u;
        }
    }
    if (tid < 128) {
        reinterpret_cast<float*>(dyn + NO_B2)[tid] = lin2b[tid];
        reinterpret_cast<float*>(dyn + NO_BL)[tid] = linb[tid];
    }
    const float* b2s = reinterpret_cast<const float*>(dyn + NO_B2);
    const float* bls = reinterpret_cast<const float*>(dyn + NO_BL);
    float* hf = reinterpret_cast<float*>(dyn + NO_HF32);

    int ntiles = (N + 63) >> 6;
    for (int t = blockIdx.x; t < ntiles; t += gridDim.x) {
        int r0 = t << 6;
        __syncthreads();   // prev tile fully done

        // stage h (fp32 + fp16) and m_i (fp16); zero g_mi for next edge pass
        for (int idx = tid; idx < 64 * 32; idx += NTHREADS) {
            int r = idx >> 5, c4 = idx & 31;
            int gr = r0 + r;
            float4 hv = make_float4(0.f, 0.f, 0.f, 0.f);
            float4 mv = hv;
            if (gr < N) {
                hv = *reinterpret_cast<const float4*>(g_h + (size_t)gr * D + c4 * 4);
                mv = *reinterpret_cast<const float4*>(g_mi + (size_t)gr * D + c4 * 4);
                if (do_xf)
                    *reinterpret_cast<float4*>(g_mi + (size_t)gr * D + c4 * 4) =
                        make_float4(0.f, 0.f, 0.f, 0.f);
            }
            *reinterpret_cast<float4*>(hf + r * 132 + c4 * 4) = hv;
            uint2 uh; uh.x = pack_half2(hv.x, hv.y); uh.y = pack_half2(hv.z, hv.w);
            *reinterpret_cast<uint2*>(dyn + NO_H16 + r * 272 + c4 * 8) = uh;
            uint2 um; um.x = pack_half2(mv.x, mv.y); um.y = pack_half2(mv.z, mv.w);
            *reinterpret_cast<uint2*>(dyn + NO_M16 + r * 272 + c4 * 8) = um;
        }
        __syncthreads();

        // GEMM m: Cm = m_i @ lin2^T
        float accm[4][4];
#pragma unroll
        for (int nt = 0; nt < 4; nt++)
#pragma unroll
            for (int i = 0; i < 4; i++) accm[nt][i] = 0.f;
#pragma unroll
        for (int ks = 0; ks < 8; ks++) {
            int k0h = ks * 16;
            uint32_t af[4], bf[2][4];
            LDSM_X4(af, sb + NO_M16 + (wm + (lane & 15)) * 272 +
                        (k0h + ((lane >> 4) << 3)) * 2);
#pragma unroll
            for (int p = 0; p < 2; p++)
                LDSM_X4(bf[p], sb + NO_L2N +
                    (wn + p * 16 + ((lane >> 4) << 3) + (lane & 7)) * 272 +
                    (k0h + (((lane >> 3) & 1) << 3)) * 2);
#pragma unroll
            for (int nt = 0; nt < 4; nt++)
                mma_f16(accm[nt], af, &bf[nt >> 1][(nt & 1) * 2], accm[nt]);
        }
        // m = ssp(Cm + b2) -> regs
        uint32_t mlo[4], mhi[4];
        int rowa = wm + qr;
#pragma unroll
        for (int nt = 0; nt < 4; nt++) {
            int col = wn + nt * 8 + qc * 2;
            float bb0 = b2s[col], bb1 = b2s[col + 1];
            mlo[nt] = pack_half2(ssp_f(accm[nt][0] + bb0), ssp_f(accm[nt][1] + bb1));
            mhi[nt] = pack_half2(ssp_f(accm[nt][2] + bb0), ssp_f(accm[nt][3] + bb1));
        }
        __syncthreads();   // all m_i reads done
#pragma unroll
        for (int nt = 0; nt < 4; nt++) {
            int col = wn + nt * 8 + qc * 2;
            *reinterpret_cast<uint32_t*>(dyn + NO_M16 + rowa * 272 + col * 2) = mlo[nt];
            *reinterpret_cast<uint32_t*>(dyn + NO_M16 + (rowa + 8) * 272 + col * 2) = mhi[nt];
        }
        __syncthreads();

        // GEMM out: acco = h@lwA + m@lwB
        float acco[4][4];
#pragma unroll
        for (int nt = 0; nt < 4; nt++)
#pragma unroll
            for (int i = 0; i < 4; i++) acco[nt][i] = 0.f;
#pragma unroll
        for (int ks = 0; ks < 8; ks++) {
            int k0h = ks * 16;
            uint32_t afh[4], afm[4], bfa[2][4], bfb[2][4];
            LDSM_X4(afh, sb + NO_H16 + (wm + (lane & 15)) * 272 +
                         (k0h + ((lane >> 4) << 3)) * 2);
            LDSM_X4(afm, sb + NO_M16 + (wm + (lane & 15)) * 272 +
                         (k0h + ((lane >> 4) << 3)) * 2);
#pragma unroll
            for (int p = 0; p < 2; p++) {
                uint32_t roff = (wn + p * 16 + ((lane >> 4) << 3) + (lane & 7)) * 272 +
                                (k0h + (((lane >> 3) & 1) << 3)) * 2;
                LDSM_X4(bfa[p], sb + NO_LAN + roff);
                LDSM_X4(bfb[p], sb + NO_LBN + roff);
            }
#pragma unroll
            for (int nt = 0; nt < 4; nt++) {
                mma_f16(acco[nt], afh, &bfa[nt >> 1][(nt & 1) * 2], acco[nt]);
                mma_f16(acco[nt], afm, &bfb[nt >> 1][(nt & 1) * 2], acco[nt]);
            }
        }
        // out = h + acco + bl -> global (+ keep for xf)
        float2 olo[4], ohi[4];
        int gr0 = r0 + rowa, gr1 = gr0 + 8;
#pragma unroll
        for (int nt = 0; nt < 4; nt++) {
            int col = wn + nt * 8 + qc * 2;
            float bb0 = bls[col], bb1 = bls[col + 1];
            float2 h0 = *reinterpret_cast<const float2*>(hf + rowa * 132 + col);
            float2 h1 = *reinterpret_cast<const float2*>(hf + (rowa + 8) * 132 + col);
            olo[nt].x = h0.x + acco[nt][0] + bb0;
            olo[nt].y = h0.y + acco[nt][1] + bb1;
            ohi[nt].x = h1.x + acco[nt][2] + bb0;
            ohi[nt].y = h1.y + acco[nt][3] + bb1;
            if (gr0 < N)
                *reinterpret_cast<float2*>(outp + (size_t)gr0 * D + col) = olo[nt];
            if (gr1 < N)
                *reinterpret_cast<float2*>(outp + (size_t)gr1 * D + col) = ohi[nt];
        }

        if (do_xf) {
            __syncthreads();   // H16 GEMM reads done before overwrite
#pragma unroll
            for (int nt = 0; nt < 4; nt++) {
                int col = wn + nt * 8 + qc * 2;
                *reinterpret_cast<uint32_t*>(dyn + NO_H16 + rowa * 272 + col * 2) =
                    pack_half2(olo[nt].x, olo[nt].y);
                *reinterpret_cast<uint32_t*>(dyn + NO_H16 + (rowa + 8) * 272 + col * 2) =
                    pack_half2(ohi[nt].x, ohi[nt].y);
            }
            __syncthreads();

            // GEMM xf: accx = h_new @ lin1(next)^T
            float accx[4][4];
#pragma unroll
            for (int nt = 0; nt < 4; nt++)
#pragma unroll
                for (int i = 0; i < 4; i++) accx[nt][i] = 0.f;
#pragma unroll
            for (int ks = 0; ks < 8; ks++) {
                int k0h = ks * 16;
                uint32_t af[4], bf[2][4];
                LDSM_X4(af, sb + NO_H16 + (wm + (lane & 15)) * 272 +
                            (k0h + ((lane >> 4) << 3)) * 2);
#pragma unroll
                for (int p = 0; p < 2; p++)
                    LDSM_X4(bf[p], sb + NO_L1N +
                        (wn + p * 16 + ((lane >> 4) << 3) + (lane & 7)) * 272 +
                        (k0h + (((lane >> 3) & 1) << 3)) * 2);
#pragma unroll
                for (int nt = 0; nt < 4; nt++)
                    mma_f16(accx[nt], af, &bf[nt >> 1][(nt & 1) * 2], accx[nt]);
            }
#pragma unroll
            for (int nt = 0; nt < 4; nt++) {
                int col = wn + nt * 8 + qc * 2;
                float2 lo, hi;
                lo.x = accx[nt][0]; lo.y = accx[nt][1];
                hi.x = accx[nt][2]; hi.y = accx[nt][3];
                if (gr0 < N)
                    *reinterpret_cast<float2*>(g_xf + (size_t)gr0 * D + col) = lo;
                if (gr1 < N)
                    *reinterpret_cast<float2*>(g_xf + (size_t)gr1 * D + col) = hi;
            }
        }
    }
}

// ---------------- launch ----------------
extern "C" void kernel_launch(void* const* d_in, const int* in_sizes, int n_in,
                              void* d_out, int out_size) {
    const float* z    = (const float*)d_in[0];
    const int*   eidx = (const int*)d_in[1];
    const float* elen = (const float*)d_in[2];
    const float* attr = (const float*)d_in[3];
    const float* embw = (const float*)d_in[4];
    const float* embb = (const float*)d_in[5];
    const float* w1   = (const float*)d_in[6];
    const float* b1   = (const float*)d_in[7];
    const float* w2   = (const float*)d_in[8];
    const float* b2   = (const float*)d_in[9];
    const float* l1w  = (const float*)d_in[10];
    const float* l2w  = (const float*)d_in[11];
    const float* l2b  = (const float*)d_in[12];
    const float* lw   = (const float*)d_in[13];
    const float* lb   = (const float*)d_in[14];

    int N = in_sizes[0] / ZDIM;
    int E = in_sizes[2];

    const int XF_SMEM = (D * D + 64 * D) * 4;

    cudaFuncSetAttribute(xf_kernel,   cudaFuncAttributeMaxDynamicSharedMemorySize, XF_SMEM);
    cudaFuncSetAttribute(edge_kernel, cudaFuncAttributeMaxDynamicSharedMemorySize, EDGE_SMEM);
    cudaFuncSetAttribute(node_kernel, cudaFuncAttributeMaxDynamicSharedMemorySize, NODE_SMEM);

    int nsm = 148;
    cudaDeviceGetAttribute(&nsm, cudaDevAttrMultiProcessorCount, 0);

    int etiles = (E + 127) >> 7;
    int xtiles = (N + 63) >> 6;
    int ntn    = (N + 63) >> 6;
    int gx = 2 * nsm < xtiles ? 2 * nsm : xtiles;
    int ge = nsm < etiles ? nsm : etiles;
    int gn = nsm < ntn ? nsm : ntn;

    embed_kernel<<<(N * D + 255) / 256, 256>>>(z, embw, embb, N);
    xf_kernel<<<gx, 256, XF_SMEM>>>(l1w, N);   // lin1[0] + zero m_i

    for (int l = 0; l < NLAYERS; l++) {
        edge_kernel<<<ge, ETHREADS, EDGE_SMEM>>>(attr, eidx, elen,
                                            w1 + (size_t)l * D * G, b1 + (size_t)l * D,
                                            w2 + (size_t)l * D * D, b2 + (size_t)l * D, E);
        int do_xf = (l < NLAYERS - 1);
        const float* lin1n = do_xf ? (l1w + (size_t)(l + 1) * D * D) : l1w;
        int to_dout = (l == NLAYERS - 1) ? 1 : 0;
        node_kernel<<<gn, NTHREADS, NODE_SMEM>>>(
            l2w + (size_t)l * D * D, l2b + (size_t)l * D,
            lw + (size_t)l * D * 2 * D, lb + (size_t)l * D,
            lin1n, N, (float*)d_out, to_dout, do_xf);
    }
}